// round 2
// baseline (speedup 1.0000x reference)
#include <cuda_runtime.h>
#include <math.h>

#define NROWS 4096
#define DDIM  512
#define INV_TAU 5.0f
#define EPS_  1e-15f
#define L2EPS 1e-12f

// ---------------- scratch (static device allocations; no cudaMalloc) ------
__device__ float g_T [NROWS * DDIM];   // projector intermediate
__device__ float g_h1[NROWS * DDIM];   // h1 -> normalized a (in place)
__device__ float g_h2[NROWS * DDIM];   // h2 -> normalized b (in place)
__device__ float g_rowloss[2 * NROWS]; // per-row infonce losses (2 directions)
__device__ float g_gl[4 * NROWS];      // pl1, nl1, pl2, nl2 per row
__device__ float g_s[2 * DDIM];        // readout means s1, s2
__device__ float g_summ[2 * DDIM];     // W @ proj(s) for both directions

__device__ __forceinline__ float* scratch_ptr(int sel)
{
    return sel == 0 ? g_T : (sel == 1 ? g_h1 : g_h2);
}

// ---------------- GEMM: C = A(MxK) * B(NcolsxK)^T + bias, optional PReLU ---
// Aext == nullptr -> A = g_T.  dst_sel picks the output scratch buffer.
__global__ __launch_bounds__(256) void gemm_abT_kernel(
    const float* __restrict__ Aext, const float* __restrict__ B,
    const float* __restrict__ bias, const float* __restrict__ prelu_a,
    int dst_sel)
{
    const float* A = Aext ? Aext : g_T;
    float* C = scratch_ptr(dst_sel);

    __shared__ float As[32][64];
    __shared__ float Bs[32][64];
    const int I = blockIdx.x * 64;
    const int J = blockIdx.y * 64;
    const int t  = threadIdx.x;
    const int tx = t & 15, ty = t >> 4;
    const int lr = t >> 2;          // 0..63 (tile row loaded by this thread)
    const int lk = (t & 3) * 8;     // 0,8,16,24 (k offset loaded)
    float c[4][4] = {};
    const float* Ap = A + (size_t)(I + lr) * DDIM + lk;
    const float* Bp = B + (size_t)(J + lr) * DDIM + lk;

    for (int kk = 0; kk < DDIM; kk += 32) {
        float4 a0 = *(const float4*)(Ap + kk);
        float4 a1 = *(const float4*)(Ap + kk + 4);
        float4 b0 = *(const float4*)(Bp + kk);
        float4 b1 = *(const float4*)(Bp + kk + 4);
        As[lk+0][lr]=a0.x; As[lk+1][lr]=a0.y; As[lk+2][lr]=a0.z; As[lk+3][lr]=a0.w;
        As[lk+4][lr]=a1.x; As[lk+5][lr]=a1.y; As[lk+6][lr]=a1.z; As[lk+7][lr]=a1.w;
        Bs[lk+0][lr]=b0.x; Bs[lk+1][lr]=b0.y; Bs[lk+2][lr]=b0.z; Bs[lk+3][lr]=b0.w;
        Bs[lk+4][lr]=b1.x; Bs[lk+5][lr]=b1.y; Bs[lk+6][lr]=b1.z; Bs[lk+7][lr]=b1.w;
        __syncthreads();
        #pragma unroll
        for (int k = 0; k < 32; k++) {
            float4 xv = *(const float4*)&As[k][ty*4];
            float4 yv = *(const float4*)&Bs[k][tx*4];
            float xr[4] = {xv.x, xv.y, xv.z, xv.w};
            float yr[4] = {yv.x, yv.y, yv.z, yv.w};
            #pragma unroll
            for (int r = 0; r < 4; r++)
                #pragma unroll
                for (int cc = 0; cc < 4; cc++)
                    c[r][cc] += xr[r] * yr[cc];
        }
        __syncthreads();
    }

    const bool do_prelu = (prelu_a != nullptr);
    const float pa = do_prelu ? prelu_a[0] : 0.0f;
    #pragma unroll
    for (int r = 0; r < 4; r++) {
        int row = I + ty*4 + r;
        float4 o;
        float* op = &o.x;
        #pragma unroll
        for (int cc = 0; cc < 4; cc++) {
            float v = c[r][cc] + bias[J + tx*4 + cc];
            if (do_prelu) v = (v >= 0.0f) ? v : pa * v;
            op[cc] = v;
        }
        *(float4*)&C[(size_t)row * DDIM + J + tx*4] = o;
    }
}

// ---------------- row L2 normalization (in place) --------------------------
__global__ __launch_bounds__(128) void l2norm_kernel()
{
    float* h = blockIdx.y ? g_h2 : g_h1;
    const int row = blockIdx.x;
    const int t = threadIdx.x;  // 128 threads, one float4 each
    float4 v = *(float4*)&h[(size_t)row * DDIM + t*4];
    float ss = v.x*v.x + v.y*v.y + v.z*v.z + v.w*v.w;
    #pragma unroll
    for (int off = 16; off; off >>= 1) ss += __shfl_down_sync(0xffffffffu, ss, off);
    __shared__ float sm[4];
    __shared__ float stot;
    if ((t & 31) == 0) sm[t >> 5] = ss;
    __syncthreads();
    if (t == 0) stot = sm[0] + sm[1] + sm[2] + sm[3];
    __syncthreads();
    float scale = 1.0f / fmaxf(sqrtf(stot), L2EPS);
    v.x *= scale; v.y *= scale; v.z *= scale; v.w *= scale;
    *(float4*)&h[(size_t)row * DDIM + t*4] = v;
}

// ---------------- fused InfoNCE (flash-style, no NxN materialization) ------
// pass 0: X=a, Y1=a, Y2=b, mask(i,j)=m[i,j]   -> infonce(h1,h2,m)
// pass 1: X=b, Y1=b, Y2=a, mask(i,j)=m[j,i]   -> infonce(h2,h1,m.T)
__global__ __launch_bounds__(256) void infonce_kernel(const int* __restrict__ mask)
{
    const int pass = blockIdx.y;
    const float* X  = pass ? g_h2 : g_h1;
    const float* Y1 = pass ? g_h2 : g_h1;
    const float* Y2 = pass ? g_h1 : g_h2;
    __shared__ float Xs[32][64], Y1s[32][64], Y2s[32][64];
    const int I = blockIdx.x * 64;
    const int t  = threadIdx.x;
    const int tx = t & 15, ty = t >> 4;
    const int lr = t >> 2, lk = (t & 3) * 8;

    float s1a[4] = {}, s2a[4] = {}, m1a[4] = {}, m2a[4] = {};
    const float* Xp = X + (size_t)(I + lr) * DDIM + lk;

    for (int J = 0; J < NROWS; J += 64) {
        float c1[4][4] = {}, c2[4][4] = {};
        const float* Y1p = Y1 + (size_t)(J + lr) * DDIM + lk;
        const float* Y2p = Y2 + (size_t)(J + lr) * DDIM + lk;
        for (int kk = 0; kk < DDIM; kk += 32) {
            float4 x0 = *(const float4*)(Xp  + kk), x1 = *(const float4*)(Xp  + kk + 4);
            float4 p0 = *(const float4*)(Y1p + kk), p1 = *(const float4*)(Y1p + kk + 4);
            float4 q0 = *(const float4*)(Y2p + kk), q1 = *(const float4*)(Y2p + kk + 4);
            Xs [lk+0][lr]=x0.x; Xs [lk+1][lr]=x0.y; Xs [lk+2][lr]=x0.z; Xs [lk+3][lr]=x0.w;
            Xs [lk+4][lr]=x1.x; Xs [lk+5][lr]=x1.y; Xs [lk+6][lr]=x1.z; Xs [lk+7][lr]=x1.w;
            Y1s[lk+0][lr]=p0.x; Y1s[lk+1][lr]=p0.y; Y1s[lk+2][lr]=p0.z; Y1s[lk+3][lr]=p0.w;
            Y1s[lk+4][lr]=p1.x; Y1s[lk+5][lr]=p1.y; Y1s[lk+6][lr]=p1.z; Y1s[lk+7][lr]=p1.w;
            Y2s[lk+0][lr]=q0.x; Y2s[lk+1][lr]=q0.y; Y2s[lk+2][lr]=q0.z; Y2s[lk+3][lr]=q0.w;
            Y2s[lk+4][lr]=q1.x; Y2s[lk+5][lr]=q1.y; Y2s[lk+6][lr]=q1.z; Y2s[lk+7][lr]=q1.w;
            __syncthreads();
            #pragma unroll
            for (int k = 0; k < 32; k++) {
                float4 xv = *(const float4*)&Xs [k][ty*4];
                float4 av = *(const float4*)&Y1s[k][tx*4];
                float4 bv = *(const float4*)&Y2s[k][tx*4];
                float xr[4] = {xv.x, xv.y, xv.z, xv.w};
                float ar[4] = {av.x, av.y, av.z, av.w};
                float br[4] = {bv.x, bv.y, bv.z, bv.w};
                #pragma unroll
                for (int r = 0; r < 4; r++)
                    #pragma unroll
                    for (int cc = 0; cc < 4; cc++) {
                        c1[r][cc] += xr[r] * ar[cc];
                        c2[r][cc] += xr[r] * br[cc];
                    }
            }
            __syncthreads();
        }
        // exp + masked row-sum accumulation for this J tile
        #pragma unroll
        for (int r = 0; r < 4; r++) {
            int gi = I + ty*4 + r;
            #pragma unroll
            for (int cc = 0; cc < 4; cc++) {
                int gj = J + tx*4 + cc;
                float mv = (float)(pass ? mask[(size_t)gj * NROWS + gi]
                                        : mask[(size_t)gi * NROWS + gj]);
                float e1 = __expf(c1[r][cc] * INV_TAU);
                float e2 = __expf(c2[r][cc] * INV_TAU);
                s1a[r] += e1;      s2a[r] += e2;
                m1a[r] += e1 * mv; m2a[r] += e2 * mv;
            }
        }
    }
    // reduce across the 16 tx lanes owning the same rows
    #pragma unroll
    for (int r = 0; r < 4; r++) {
        #pragma unroll
        for (int off = 8; off; off >>= 1) {
            s1a[r] += __shfl_down_sync(0xffffffffu, s1a[r], off, 16);
            s2a[r] += __shfl_down_sync(0xffffffffu, s2a[r], off, 16);
            m1a[r] += __shfl_down_sync(0xffffffffu, m1a[r], off, 16);
            m2a[r] += __shfl_down_sync(0xffffffffu, m2a[r], off, 16);
        }
        if (tx == 0) {
            float den = s1a[r] + s2a[r] - m1a[r];
            g_rowloss[pass * NROWS + I + ty*4 + r] = -logf(m2a[r] / den);
        }
    }
}

// ---------------- column means of z1, z2 (readout s) -----------------------
__global__ __launch_bounds__(512) void colmean_kernel(const float* __restrict__ z1,
                                                      const float* __restrict__ z2)
{
    const float* z = blockIdx.x ? z2 : z1;
    const int t = threadIdx.x;  // one column per thread
    float a0 = 0, a1 = 0, a2 = 0, a3 = 0;
    for (int r = 0; r < NROWS; r += 4) {
        a0 += z[(size_t)(r+0) * DDIM + t];
        a1 += z[(size_t)(r+1) * DDIM + t];
        a2 += z[(size_t)(r+2) * DDIM + t];
        a3 += z[(size_t)(r+3) * DDIM + t];
    }
    g_s[blockIdx.x * DDIM + t] = (a0 + a1 + a2 + a3) * (1.0f / NROWS);
}

// ---------------- global projector chain: summ_p = W @ proj(s_p) -----------
__device__ __forceinline__ void mv_stage(const float* __restrict__ Wm,
                                         const float* __restrict__ bias,
                                         const float* vin, float* vout,
                                         float pa, bool prelu_on,
                                         int warp, int lane)
{
    for (int rr = 0; rr < 32; rr++) {
        int o = warp * 32 + rr;
        const float* wr = Wm + (size_t)o * DDIM;
        float acc = 0.0f;
        for (int i = lane; i < DDIM; i += 32) acc += wr[i] * vin[i];
        #pragma unroll
        for (int off = 16; off; off >>= 1) acc += __shfl_down_sync(0xffffffffu, acc, off);
        if (lane == 0) {
            float v = acc + (bias ? bias[o] : 0.0f);
            if (prelu_on) v = (v >= 0.0f) ? v : pa * v;
            vout[o] = v;
        }
    }
}

__global__ __launch_bounds__(512) void gproj_kernel(
    const float* __restrict__ gw1, const float* __restrict__ gb1,
    const float* __restrict__ ga,  const float* __restrict__ gw2,
    const float* __restrict__ gb2, const float* __restrict__ W)
{
    __shared__ float v[DDIM], u[DDIM], hh[DDIM];
    const int p = blockIdx.x;
    const int t = threadIdx.x, warp = t >> 5, lane = t & 31;
    v[t] = g_s[p * DDIM + t];
    __syncthreads();
    mv_stage(gw1, gb1, v, u, ga[0], true, warp, lane);
    __syncthreads();
    mv_stage(gw2, gb2, u, hh, 0.0f, false, warp, lane);
    __syncthreads();
    // summ = W @ hh
    for (int rr = 0; rr < 32; rr++) {
        int o = warp * 32 + rr;
        const float* wr = W + (size_t)o * DDIM;
        float acc = 0.0f;
        for (int i = lane; i < DDIM; i += 32) acc += wr[i] * hh[i];
        #pragma unroll
        for (int off = 16; off; off >>= 1) acc += __shfl_down_sync(0xffffffffu, acc, off);
        if (lane == 0) g_summ[p * DDIM + o] = acc;
    }
}

// ---------------- per-row discriminator terms ------------------------------
__global__ __launch_bounds__(256) void sigrows_kernel(const float* __restrict__ z1,
                                                      const float* __restrict__ z2)
{
    const int warp = threadIdx.x >> 5, lane = threadIdx.x & 31;
    const int row = blockIdx.x * 8 + warp;
    const float* r1 = z1 + (size_t)row * DDIM;
    const float* r2 = z2 + (size_t)row * DDIM;
    float d11 = 0, d12 = 0, d21 = 0, d22 = 0;
    for (int i = lane; i < DDIM; i += 32) {
        float a = r1[i], b = r2[i];
        float s1 = g_summ[i], s2 = g_summ[DDIM + i];
        d11 += a * s1; d12 += a * s2; d21 += b * s1; d22 += b * s2;
    }
    #pragma unroll
    for (int off = 16; off; off >>= 1) {
        d11 += __shfl_down_sync(0xffffffffu, d11, off);
        d12 += __shfl_down_sync(0xffffffffu, d12, off);
        d21 += __shfl_down_sync(0xffffffffu, d21, off);
        d22 += __shfl_down_sync(0xffffffffu, d22, off);
    }
    if (lane == 0) {
        float sg11 = 1.0f / (1.0f + expf(-d11));
        float sg21 = 1.0f / (1.0f + expf(-d21));
        float sg22 = 1.0f / (1.0f + expf(-d22));
        float sg12 = 1.0f / (1.0f + expf(-d12));
        g_gl[0 * NROWS + row] = -logf(sg11 + EPS_);          // pos for gloss(z1,z2)
        g_gl[1 * NROWS + row] = -logf(1.0f - sg21 + EPS_);   // neg for gloss(z1,z2)
        g_gl[2 * NROWS + row] = -logf(sg22 + EPS_);          // pos for gloss(z2,z1)
        g_gl[3 * NROWS + row] = -logf(1.0f - sg12 + EPS_);   // neg for gloss(z2,z1)
    }
}

// ---------------- final deterministic reduction ----------------------------
__global__ __launch_bounds__(1024) void finalize_kernel(float* __restrict__ out)
{
    __shared__ float red[32];
    float acc[6] = {0, 0, 0, 0, 0, 0};
    for (int i = threadIdx.x; i < NROWS; i += 1024) {
        acc[0] += g_rowloss[i];
        acc[1] += g_rowloss[NROWS + i];
        acc[2] += g_gl[i];
        acc[3] += g_gl[NROWS + i];
        acc[4] += g_gl[2 * NROWS + i];
        acc[5] += g_gl[3 * NROWS + i];
    }
    const int lane = threadIdx.x & 31, warp = threadIdx.x >> 5;
    float tot[6];
    for (int q = 0; q < 6; q++) {
        float v = acc[q];
        #pragma unroll
        for (int off = 16; off; off >>= 1) v += __shfl_down_sync(0xffffffffu, v, off);
        if (lane == 0) red[warp] = v;
        __syncthreads();
        if (warp == 0) {
            float w = red[lane];
            #pragma unroll
            for (int off = 16; off; off >>= 1) w += __shfl_down_sync(0xffffffffu, w, off);
            if (lane == 0) tot[q] = w;
        }
        __syncthreads();
    }
    if (threadIdx.x == 0) {
        const float inv = 1.0f / NROWS;
        float local = 0.5f * (tot[0] + tot[1]) * inv;
        float gl1   = 0.5f * (tot[2] + tot[3]) * inv;
        float gl2   = 0.5f * (tot[4] + tot[5]) * inv;
        float glob  = 0.5f * (gl1 + gl2);
        out[0] = 0.5f * local + 0.5f * glob;   // ALPHA = 0.5
    }
}

// ---------------- launch ----------------------------------------------------
extern "C" void kernel_launch(void* const* d_in, const int* in_sizes, int n_in,
                              void* d_out, int out_size)
{
    const float* z1  = (const float*)d_in[0];
    const float* z2  = (const float*)d_in[1];
    const float* lw1 = (const float*)d_in[2];
    const float* lb1 = (const float*)d_in[3];
    const float* la  = (const float*)d_in[4];
    const float* lw2 = (const float*)d_in[5];
    const float* lb2 = (const float*)d_in[6];
    const float* gw1 = (const float*)d_in[7];
    const float* gb1 = (const float*)d_in[8];
    const float* ga  = (const float*)d_in[9];
    const float* gw2 = (const float*)d_in[10];
    const float* gb2 = (const float*)d_in[11];
    const float* W   = (const float*)d_in[12];
    const int*   mask= (const int*)  d_in[13];
    float* out = (float*)d_out;

    dim3 gemm_grid(NROWS / 64, DDIM / 64);

    // local projector: h1 = prelu(z1@lw1^T + lb1) @ lw2^T + lb2 ; same for z2
    gemm_abT_kernel<<<gemm_grid, 256>>>(z1,      lw1, lb1, la,      0); // T  = prelu(z1@lw1^T+lb1)
    gemm_abT_kernel<<<gemm_grid, 256>>>(nullptr, lw2, lb2, nullptr, 1); // h1 = T@lw2^T+lb2
    gemm_abT_kernel<<<gemm_grid, 256>>>(z2,      lw1, lb1, la,      0); // T  = prelu(z2@lw1^T+lb1)
    gemm_abT_kernel<<<gemm_grid, 256>>>(nullptr, lw2, lb2, nullptr, 2); // h2 = T@lw2^T+lb2

    // normalize rows of h1, h2 in place
    l2norm_kernel<<<dim3(NROWS, 2), 128>>>();

    // fused InfoNCE, both directions
    infonce_kernel<<<dim3(NROWS / 64, 2), 256>>>(mask);

    // global (DGI-style) loss
    colmean_kernel<<<2, DDIM>>>(z1, z2);
    gproj_kernel<<<2, DDIM>>>(gw1, gb1, ga, gw2, gb2, W);
    sigrows_kernel<<<NROWS / 8, 256>>>(z1, z2);

    finalize_kernel<<<1, 1024>>>(out);
}

// round 3
// speedup vs baseline: 1.4771x; 1.4771x over previous
#include <cuda_runtime.h>
#include <math.h>

#define NROWS 4096
#define DDIM  512
#define INV_TAU 5.0f
#define EPS_  1e-15f
#define L2EPS 1e-12f

#define NCHUNK 4
#define CHUNKJ (NROWS / NCHUNK)   // 1024
#define JT 128
#define IT 64
#define NIB (NROWS / IT)          // 64

typedef unsigned long long u64;

// ---------------- scratch (static device allocations; no cudaMalloc) ------
__device__ float g_T [NROWS * DDIM];
__device__ float g_h1[NROWS * DDIM];
__device__ float g_h2[NROWS * DDIM];
__device__ float g_rowloss[2 * NROWS];
__device__ float g_gl[4 * NROWS];
__device__ float g_s[2 * DDIM];
__device__ float g_summ[2 * DDIM];
__device__ float g_rpA[NCHUNK][4][NROWS];   // pass0 row partials: aaS, aaM, abS, abM
__device__ float g_rpB[NCHUNK][2][NROWS];   // pass1 row partials: bbS, bbM
__device__ float g_cp[2][NIB][NROWS];       // E2 column partials: S, M

__device__ __forceinline__ float* scratch_ptr(int sel)
{
    return sel == 0 ? g_T : (sel == 1 ? g_h1 : g_h2);
}

// ---------------- f32x2 helpers --------------------------------------------
__device__ __forceinline__ u64 pk2(float lo, float hi)
{
    u64 r;
    asm("mov.b64 %0, {%1, %2};" : "=l"(r) : "f"(lo), "f"(hi));
    return r;
}
__device__ __forceinline__ void ffma2(u64& acc, u64 a, u64 b)
{
    asm("fma.rn.f32x2 %0, %1, %2, %0;" : "+l"(acc) : "l"(a), "l"(b));
}
__device__ __forceinline__ void unpk2(u64 v, float& lo, float& hi)
{
    asm("mov.b64 {%0, %1}, %2;" : "=f"(lo), "=f"(hi) : "l"(v));
}

// ---------------- GEMM: C = A(MxK) * B(NcolsxK)^T + bias, optional PReLU ---
__global__ __launch_bounds__(256) void gemm_abT_kernel(
    const float* __restrict__ Aext, const float* __restrict__ B,
    const float* __restrict__ bias, const float* __restrict__ prelu_a,
    int dst_sel)
{
    const float* A = Aext ? Aext : g_T;
    float* C = scratch_ptr(dst_sel);

    __shared__ float As[32][64];
    __shared__ float Bs[32][64];
    const int I = blockIdx.x * 64;
    const int J = blockIdx.y * 64;
    const int t  = threadIdx.x;
    const int tx = t & 15, ty = t >> 4;
    const int lr = t >> 2;
    const int lk = (t & 3) * 8;
    float c[4][4] = {};
    const float* Ap = A + (size_t)(I + lr) * DDIM + lk;
    const float* Bp = B + (size_t)(J + lr) * DDIM + lk;

    for (int kk = 0; kk < DDIM; kk += 32) {
        float4 a0 = *(const float4*)(Ap + kk);
        float4 a1 = *(const float4*)(Ap + kk + 4);
        float4 b0 = *(const float4*)(Bp + kk);
        float4 b1 = *(const float4*)(Bp + kk + 4);
        As[lk+0][lr]=a0.x; As[lk+1][lr]=a0.y; As[lk+2][lr]=a0.z; As[lk+3][lr]=a0.w;
        As[lk+4][lr]=a1.x; As[lk+5][lr]=a1.y; As[lk+6][lr]=a1.z; As[lk+7][lr]=a1.w;
        Bs[lk+0][lr]=b0.x; Bs[lk+1][lr]=b0.y; Bs[lk+2][lr]=b0.z; Bs[lk+3][lr]=b0.w;
        Bs[lk+4][lr]=b1.x; Bs[lk+5][lr]=b1.y; Bs[lk+6][lr]=b1.z; Bs[lk+7][lr]=b1.w;
        __syncthreads();
        #pragma unroll
        for (int k = 0; k < 32; k++) {
            float4 xv = *(const float4*)&As[k][ty*4];
            float4 yv = *(const float4*)&Bs[k][tx*4];
            float xr[4] = {xv.x, xv.y, xv.z, xv.w};
            float yr[4] = {yv.x, yv.y, yv.z, yv.w};
            #pragma unroll
            for (int r = 0; r < 4; r++)
                #pragma unroll
                for (int cc = 0; cc < 4; cc++)
                    c[r][cc] += xr[r] * yr[cc];
        }
        __syncthreads();
    }

    const bool do_prelu = (prelu_a != nullptr);
    const float pa = do_prelu ? prelu_a[0] : 0.0f;
    #pragma unroll
    for (int r = 0; r < 4; r++) {
        int row = I + ty*4 + r;
        float4 o;
        float* op = &o.x;
        #pragma unroll
        for (int cc = 0; cc < 4; cc++) {
            float v = c[r][cc] + bias[J + tx*4 + cc];
            if (do_prelu) v = (v >= 0.0f) ? v : pa * v;
            op[cc] = v;
        }
        *(float4*)&C[(size_t)row * DDIM + J + tx*4] = o;
    }
}

// ---------------- row L2 normalization (in place) --------------------------
__global__ __launch_bounds__(128) void l2norm_kernel()
{
    float* h = blockIdx.y ? g_h2 : g_h1;
    const int row = blockIdx.x;
    const int t = threadIdx.x;
    float4 v = *(float4*)&h[(size_t)row * DDIM + t*4];
    float ss = v.x*v.x + v.y*v.y + v.z*v.z + v.w*v.w;
    #pragma unroll
    for (int off = 16; off; off >>= 1) ss += __shfl_down_sync(0xffffffffu, ss, off);
    __shared__ float sm[4];
    __shared__ float stot;
    if ((t & 31) == 0) sm[t >> 5] = ss;
    __syncthreads();
    if (t == 0) stot = sm[0] + sm[1] + sm[2] + sm[3];
    __syncthreads();
    float scale = 1.0f / fmaxf(sqrtf(stot), L2EPS);
    v.x *= scale; v.y *= scale; v.z *= scale; v.w *= scale;
    *(float4*)&h[(size_t)row * DDIM + t*4] = v;
}

// ---------------- fused similarity kernel ----------------------------------
// Block (Ib, c): i-rows I..I+63 of a=g_h1 and b=g_h2; streams j in chunk c.
// Computes E1=exp(a_I.a_J/t), E2=exp(a_I.b_J/t), E3=exp(b_I.b_J/t) tiles.
// Accumulates: pass0 rows (E1 sums + masked, E2 row sums + masked),
// pass1 rows (E3 sums + masked-transposed), E2 column partials (+masked).
__global__ __launch_bounds__(256, 1) void sim_kernel(const int* __restrict__ mask)
{
    __shared__ __align__(16) float smf[12288];   // 48 KB
    float* aIs = smf;            // [32][64]
    float* bIs = smf + 2048;     // [32][64]
    float* aJs = smf + 4096;     // [32][128]
    float* bJs = smf + 8192;     // [32][128]
    float2* colred = (float2*)(smf + 4096);  // overlays aJs after compute: [16][128]

    const int Ib = blockIdx.x;
    const int c  = blockIdx.y;
    const int I  = Ib * IT;
    const int t  = threadIdx.x;
    const int tx = t & 15, ty = t >> 4;
    const int lrI = t >> 2, lkI = (t & 3) * 8;
    const int lrJ = t >> 1, lkJ = (t & 1) * 16;

    const float* __restrict__ A = g_h1;
    const float* __restrict__ B = g_h2;

    float raa_s[4] = {}, raa_m[4] = {}, rab_s[4] = {}, rab_m[4] = {};
    float rbb_s[4] = {}, rbb_m[4] = {};

    const float* aIp = A + (size_t)(I + lrI) * DDIM + lkI;
    const float* bIp = B + (size_t)(I + lrI) * DDIM + lkI;

    for (int Jt = c * CHUNKJ; Jt < (c + 1) * CHUNKJ; Jt += JT) {
        u64 aa[4][4], ab[4][4], bb[4][4];
        #pragma unroll
        for (int i = 0; i < 4; i++)
            #pragma unroll
            for (int jp = 0; jp < 4; jp++) { aa[i][jp] = 0ULL; ab[i][jp] = 0ULL; bb[i][jp] = 0ULL; }
        float cs[8] = {}, cm[8] = {};

        const float* aJp = A + (size_t)(Jt + lrJ) * DDIM + lkJ;
        const float* bJp = B + (size_t)(Jt + lrJ) * DDIM + lkJ;

        for (int kk = 0; kk < DDIM; kk += 32) {
            float4 va0 = *(const float4*)(aIp + kk);
            float4 va1 = *(const float4*)(aIp + kk + 4);
            float4 vb0 = *(const float4*)(bIp + kk);
            float4 vb1 = *(const float4*)(bIp + kk + 4);
            float4 wa0 = *(const float4*)(aJp + kk);
            float4 wa1 = *(const float4*)(aJp + kk + 4);
            float4 wa2 = *(const float4*)(aJp + kk + 8);
            float4 wa3 = *(const float4*)(aJp + kk + 12);
            float4 wb0 = *(const float4*)(bJp + kk);
            float4 wb1 = *(const float4*)(bJp + kk + 4);
            float4 wb2 = *(const float4*)(bJp + kk + 8);
            float4 wb3 = *(const float4*)(bJp + kk + 12);
            __syncthreads();   // previous slab's compute / colred reads done
            aIs[(lkI+0)*64+lrI]=va0.x; aIs[(lkI+1)*64+lrI]=va0.y;
            aIs[(lkI+2)*64+lrI]=va0.z; aIs[(lkI+3)*64+lrI]=va0.w;
            aIs[(lkI+4)*64+lrI]=va1.x; aIs[(lkI+5)*64+lrI]=va1.y;
            aIs[(lkI+6)*64+lrI]=va1.z; aIs[(lkI+7)*64+lrI]=va1.w;
            bIs[(lkI+0)*64+lrI]=vb0.x; bIs[(lkI+1)*64+lrI]=vb0.y;
            bIs[(lkI+2)*64+lrI]=vb0.z; bIs[(lkI+3)*64+lrI]=vb0.w;
            bIs[(lkI+4)*64+lrI]=vb1.x; bIs[(lkI+5)*64+lrI]=vb1.y;
            bIs[(lkI+6)*64+lrI]=vb1.z; bIs[(lkI+7)*64+lrI]=vb1.w;
            aJs[(lkJ+ 0)*128+lrJ]=wa0.x; aJs[(lkJ+ 1)*128+lrJ]=wa0.y;
            aJs[(lkJ+ 2)*128+lrJ]=wa0.z; aJs[(lkJ+ 3)*128+lrJ]=wa0.w;
            aJs[(lkJ+ 4)*128+lrJ]=wa1.x; aJs[(lkJ+ 5)*128+lrJ]=wa1.y;
            aJs[(lkJ+ 6)*128+lrJ]=wa1.z; aJs[(lkJ+ 7)*128+lrJ]=wa1.w;
            aJs[(lkJ+ 8)*128+lrJ]=wa2.x; aJs[(lkJ+ 9)*128+lrJ]=wa2.y;
            aJs[(lkJ+10)*128+lrJ]=wa2.z; aJs[(lkJ+11)*128+lrJ]=wa2.w;
            aJs[(lkJ+12)*128+lrJ]=wa3.x; aJs[(lkJ+13)*128+lrJ]=wa3.y;
            aJs[(lkJ+14)*128+lrJ]=wa3.z; aJs[(lkJ+15)*128+lrJ]=wa3.w;
            bJs[(lkJ+ 0)*128+lrJ]=wb0.x; bJs[(lkJ+ 1)*128+lrJ]=wb0.y;
            bJs[(lkJ+ 2)*128+lrJ]=wb0.z; bJs[(lkJ+ 3)*128+lrJ]=wb0.w;
            bJs[(lkJ+ 4)*128+lrJ]=wb1.x; bJs[(lkJ+ 5)*128+lrJ]=wb1.y;
            bJs[(lkJ+ 6)*128+lrJ]=wb1.z; bJs[(lkJ+ 7)*128+lrJ]=wb1.w;
            bJs[(lkJ+ 8)*128+lrJ]=wb2.x; bJs[(lkJ+ 9)*128+lrJ]=wb2.y;
            bJs[(lkJ+10)*128+lrJ]=wb2.z; bJs[(lkJ+11)*128+lrJ]=wb2.w;
            bJs[(lkJ+12)*128+lrJ]=wb3.x; bJs[(lkJ+13)*128+lrJ]=wb3.y;
            bJs[(lkJ+14)*128+lrJ]=wb3.z; bJs[(lkJ+15)*128+lrJ]=wb3.w;
            __syncthreads();
            #pragma unroll 4
            for (int k = 0; k < 32; k++) {
                float4 xa = *(const float4*)(aIs + k*64 + ty*4);
                float4 xb = *(const float4*)(bIs + k*64 + ty*4);
                ulonglong2 ya0 = *(const ulonglong2*)(aJs + k*128 + tx*8);
                ulonglong2 ya1 = *(const ulonglong2*)(aJs + k*128 + tx*8 + 4);
                ulonglong2 yb0 = *(const ulonglong2*)(bJs + k*128 + tx*8);
                ulonglong2 yb1 = *(const ulonglong2*)(bJs + k*128 + tx*8 + 4);
                float xav[4] = {xa.x, xa.y, xa.z, xa.w};
                float xbv[4] = {xb.x, xb.y, xb.z, xb.w};
                #pragma unroll
                for (int i = 0; i < 4; i++) {
                    u64 pa = pk2(xav[i], xav[i]);
                    u64 pb = pk2(xbv[i], xbv[i]);
                    ffma2(aa[i][0], pa, ya0.x); ffma2(aa[i][1], pa, ya0.y);
                    ffma2(aa[i][2], pa, ya1.x); ffma2(aa[i][3], pa, ya1.y);
                    ffma2(ab[i][0], pa, yb0.x); ffma2(ab[i][1], pa, yb0.y);
                    ffma2(ab[i][2], pa, yb1.x); ffma2(ab[i][3], pa, yb1.y);
                    ffma2(bb[i][0], pb, yb0.x); ffma2(bb[i][1], pb, yb0.y);
                    ffma2(bb[i][2], pb, yb1.x); ffma2(bb[i][3], pb, yb1.y);
                }
            }
        }
        __syncthreads();   // all compute done before smem reuse

        // ---- epilogue: exp + masked accumulation ----
        float e1[4][8], e2[4][8], e3[4][8];
        #pragma unroll
        for (int i = 0; i < 4; i++)
            #pragma unroll
            for (int jp = 0; jp < 4; jp++) {
                float lo, hi;
                unpk2(aa[i][jp], lo, hi);
                e1[i][jp*2] = __expf(lo * INV_TAU); e1[i][jp*2+1] = __expf(hi * INV_TAU);
                unpk2(ab[i][jp], lo, hi);
                e2[i][jp*2] = __expf(lo * INV_TAU); e2[i][jp*2+1] = __expf(hi * INV_TAU);
                unpk2(bb[i][jp], lo, hi);
                e3[i][jp*2] = __expf(lo * INV_TAU); e3[i][jp*2+1] = __expf(hi * INV_TAU);
            }

        #pragma unroll
        for (int i = 0; i < 4; i++) {
            int gi = I + ty*4 + i;
            int4 mA = *(const int4*)(mask + (size_t)gi * NROWS + Jt + tx*8);
            int4 mB = *(const int4*)(mask + (size_t)gi * NROWS + Jt + tx*8 + 4);
            int mrow[8] = {mA.x, mA.y, mA.z, mA.w, mB.x, mB.y, mB.z, mB.w};
            #pragma unroll
            for (int jj = 0; jj < 8; jj++) {
                float mv = (float)mrow[jj];
                raa_s[i] += e1[i][jj];
                raa_m[i] += e1[i][jj] * mv;
                rab_s[i] += e2[i][jj];
                rab_m[i] += e2[i][jj] * mv;
                rbb_s[i] += e3[i][jj];
                cs[jj]   += e2[i][jj];
                cm[jj]   += e2[i][jj] * mv;
            }
        }
        // transposed-mask term for E3 (pass1 intra masked sum uses m_ji)
        #pragma unroll
        for (int jj = 0; jj < 8; jj++) {
            int gj = Jt + tx*8 + jj;
            int4 mt4 = *(const int4*)(mask + (size_t)gj * NROWS + I + ty*4);
            int mtv[4] = {mt4.x, mt4.y, mt4.z, mt4.w};
            #pragma unroll
            for (int i = 0; i < 4; i++)
                rbb_m[i] += e3[i][jj] * (float)mtv[i];
        }

        // ---- column partial reduction (over the 16 ty groups) via smem ----
        #pragma unroll
        for (int jj = 0; jj < 8; jj++)
            colred[ty * 128 + tx*8 + jj] = make_float2(cs[jj], cm[jj]);
        __syncthreads();
        {
            int col = t & 127, q = t >> 7;
            float sum = 0.0f;
            #pragma unroll
            for (int g = 0; g < 16; g++) {
                float2 v = colred[g * 128 + col];
                sum += q ? v.y : v.x;
            }
            g_cp[q][Ib][Jt + col] = sum;
        }
        __syncthreads();   // protect colred region before next tile's smem stores
    }

    // ---- row partial reduction across the 16 tx lanes -> global ----
    #pragma unroll
    for (int i = 0; i < 4; i++) {
        #pragma unroll
        for (int off = 8; off; off >>= 1) {
            raa_s[i] += __shfl_down_sync(0xffffffffu, raa_s[i], off, 16);
            raa_m[i] += __shfl_down_sync(0xffffffffu, raa_m[i], off, 16);
            rab_s[i] += __shfl_down_sync(0xffffffffu, rab_s[i], off, 16);
            rab_m[i] += __shfl_down_sync(0xffffffffu, rab_m[i], off, 16);
            rbb_s[i] += __shfl_down_sync(0xffffffffu, rbb_s[i], off, 16);
            rbb_m[i] += __shfl_down_sync(0xffffffffu, rbb_m[i], off, 16);
        }
        if (tx == 0) {
            int gi = I + ty*4 + i;
            g_rpA[c][0][gi] = raa_s[i];
            g_rpA[c][1][gi] = raa_m[i];
            g_rpA[c][2][gi] = rab_s[i];
            g_rpA[c][3][gi] = rab_m[i];
            g_rpB[c][0][gi] = rbb_s[i];
            g_rpB[c][1][gi] = rbb_m[i];
        }
    }
}

// ---------------- combine partials -> per-row losses ------------------------
__global__ __launch_bounds__(256) void rowloss2_kernel()
{
    int i = blockIdx.x * 256 + threadIdx.x;
    float aas = 0, aam = 0, abs_ = 0, abm = 0, bbs = 0, bbm = 0;
    #pragma unroll
    for (int c = 0; c < NCHUNK; c++) {
        aas  += g_rpA[c][0][i];
        aam  += g_rpA[c][1][i];
        abs_ += g_rpA[c][2][i];
        abm  += g_rpA[c][3][i];
        bbs  += g_rpB[c][0][i];
        bbm  += g_rpB[c][1][i];
    }
    float ccs = 0, ccm = 0;
    for (int b = 0; b < NIB; b++) {
        ccs += g_cp[0][b][i];
        ccm += g_cp[1][b][i];
    }
    g_rowloss[i]         = -logf(abm / (aas + abs_ - aam));
    g_rowloss[NROWS + i] = -logf(ccm / (bbs + ccs - bbm));
}

// ---------------- column means of z1, z2 (readout s) -----------------------
__global__ __launch_bounds__(512) void colmean_kernel(const float* __restrict__ z1,
                                                      const float* __restrict__ z2)
{
    const float* z = blockIdx.x ? z2 : z1;
    const int t = threadIdx.x;
    float a0 = 0, a1 = 0, a2 = 0, a3 = 0;
    for (int r = 0; r < NROWS; r += 4) {
        a0 += z[(size_t)(r+0) * DDIM + t];
        a1 += z[(size_t)(r+1) * DDIM + t];
        a2 += z[(size_t)(r+2) * DDIM + t];
        a3 += z[(size_t)(r+3) * DDIM + t];
    }
    g_s[blockIdx.x * DDIM + t] = (a0 + a1 + a2 + a3) * (1.0f / NROWS);
}

// ---------------- global projector chain: summ_p = W @ proj(s_p) -----------
__device__ __forceinline__ void mv_stage(const float* __restrict__ Wm,
                                         const float* __restrict__ bias,
                                         const float* vin, float* vout,
                                         float pa, bool prelu_on,
                                         int warp, int lane)
{
    for (int rr = 0; rr < 32; rr++) {
        int o = warp * 32 + rr;
        const float* wr = Wm + (size_t)o * DDIM;
        float acc = 0.0f;
        for (int i = lane; i < DDIM; i += 32) acc += wr[i] * vin[i];
        #pragma unroll
        for (int off = 16; off; off >>= 1) acc += __shfl_down_sync(0xffffffffu, acc, off);
        if (lane == 0) {
            float v = acc + (bias ? bias[o] : 0.0f);
            if (prelu_on) v = (v >= 0.0f) ? v : pa * v;
            vout[o] = v;
        }
    }
}

__global__ __launch_bounds__(512) void gproj_kernel(
    const float* __restrict__ gw1, const float* __restrict__ gb1,
    const float* __restrict__ ga,  const float* __restrict__ gw2,
    const float* __restrict__ gb2, const float* __restrict__ W)
{
    __shared__ float v[DDIM], u[DDIM], hh[DDIM];
    const int p = blockIdx.x;
    const int t = threadIdx.x, warp = t >> 5, lane = t & 31;
    v[t] = g_s[p * DDIM + t];
    __syncthreads();
    mv_stage(gw1, gb1, v, u, ga[0], true, warp, lane);
    __syncthreads();
    mv_stage(gw2, gb2, u, hh, 0.0f, false, warp, lane);
    __syncthreads();
    for (int rr = 0; rr < 32; rr++) {
        int o = warp * 32 + rr;
        const float* wr = W + (size_t)o * DDIM;
        float acc = 0.0f;
        for (int i = lane; i < DDIM; i += 32) acc += wr[i] * hh[i];
        #pragma unroll
        for (int off = 16; off; off >>= 1) acc += __shfl_down_sync(0xffffffffu, acc, off);
        if (lane == 0) g_summ[p * DDIM + o] = acc;
    }
}

// ---------------- per-row discriminator terms ------------------------------
__global__ __launch_bounds__(256) void sigrows_kernel(const float* __restrict__ z1,
                                                      const float* __restrict__ z2)
{
    const int warp = threadIdx.x >> 5, lane = threadIdx.x & 31;
    const int row = blockIdx.x * 8 + warp;
    const float* r1 = z1 + (size_t)row * DDIM;
    const float* r2 = z2 + (size_t)row * DDIM;
    float d11 = 0, d12 = 0, d21 = 0, d22 = 0;
    for (int i = lane; i < DDIM; i += 32) {
        float a = r1[i], b = r2[i];
        float s1 = g_summ[i], s2 = g_summ[DDIM + i];
        d11 += a * s1; d12 += a * s2; d21 += b * s1; d22 += b * s2;
    }
    #pragma unroll
    for (int off = 16; off; off >>= 1) {
        d11 += __shfl_down_sync(0xffffffffu, d11, off);
        d12 += __shfl_down_sync(0xffffffffu, d12, off);
        d21 += __shfl_down_sync(0xffffffffu, d21, off);
        d22 += __shfl_down_sync(0xffffffffu, d22, off);
    }
    if (lane == 0) {
        float sg11 = 1.0f / (1.0f + expf(-d11));
        float sg21 = 1.0f / (1.0f + expf(-d21));
        float sg22 = 1.0f / (1.0f + expf(-d22));
        float sg12 = 1.0f / (1.0f + expf(-d12));
        g_gl[0 * NROWS + row] = -logf(sg11 + EPS_);
        g_gl[1 * NROWS + row] = -logf(1.0f - sg21 + EPS_);
        g_gl[2 * NROWS + row] = -logf(sg22 + EPS_);
        g_gl[3 * NROWS + row] = -logf(1.0f - sg12 + EPS_);
    }
}

// ---------------- final deterministic reduction ----------------------------
__global__ __launch_bounds__(1024) void finalize_kernel(float* __restrict__ out)
{
    __shared__ float red[32];
    float acc[6] = {0, 0, 0, 0, 0, 0};
    for (int i = threadIdx.x; i < NROWS; i += 1024) {
        acc[0] += g_rowloss[i];
        acc[1] += g_rowloss[NROWS + i];
        acc[2] += g_gl[i];
        acc[3] += g_gl[NROWS + i];
        acc[4] += g_gl[2 * NROWS + i];
        acc[5] += g_gl[3 * NROWS + i];
    }
    const int lane = threadIdx.x & 31, warp = threadIdx.x >> 5;
    float tot[6];
    for (int q = 0; q < 6; q++) {
        float v = acc[q];
        #pragma unroll
        for (int off = 16; off; off >>= 1) v += __shfl_down_sync(0xffffffffu, v, off);
        if (lane == 0) red[warp] = v;
        __syncthreads();
        if (warp == 0) {
            float w = red[lane];
            #pragma unroll
            for (int off = 16; off; off >>= 1) w += __shfl_down_sync(0xffffffffu, w, off);
            if (lane == 0) tot[q] = w;
        }
        __syncthreads();
    }
    if (threadIdx.x == 0) {
        const float inv = 1.0f / NROWS;
        float local = 0.5f * (tot[0] + tot[1]) * inv;
        float gl1   = 0.5f * (tot[2] + tot[3]) * inv;
        float gl2   = 0.5f * (tot[4] + tot[5]) * inv;
        float glob  = 0.5f * (gl1 + gl2);
        out[0] = 0.5f * local + 0.5f * glob;   // ALPHA = 0.5
    }
}

// ---------------- launch ----------------------------------------------------
extern "C" void kernel_launch(void* const* d_in, const int* in_sizes, int n_in,
                              void* d_out, int out_size)
{
    const float* z1  = (const float*)d_in[0];
    const float* z2  = (const float*)d_in[1];
    const float* lw1 = (const float*)d_in[2];
    const float* lb1 = (const float*)d_in[3];
    const float* la  = (const float*)d_in[4];
    const float* lw2 = (const float*)d_in[5];
    const float* lb2 = (const float*)d_in[6];
    const float* gw1 = (const float*)d_in[7];
    const float* gb1 = (const float*)d_in[8];
    const float* ga  = (const float*)d_in[9];
    const float* gw2 = (const float*)d_in[10];
    const float* gb2 = (const float*)d_in[11];
    const float* W   = (const float*)d_in[12];
    const int*   mask= (const int*)  d_in[13];
    float* out = (float*)d_out;

    dim3 gemm_grid(NROWS / 64, DDIM / 64);

    gemm_abT_kernel<<<gemm_grid, 256>>>(z1,      lw1, lb1, la,      0);
    gemm_abT_kernel<<<gemm_grid, 256>>>(nullptr, lw2, lb2, nullptr, 1);
    gemm_abT_kernel<<<gemm_grid, 256>>>(z2,      lw1, lb1, la,      0);
    gemm_abT_kernel<<<gemm_grid, 256>>>(nullptr, lw2, lb2, nullptr, 2);

    l2norm_kernel<<<dim3(NROWS, 2), 128>>>();

    sim_kernel<<<dim3(NIB, NCHUNK), 256>>>(mask);
    rowloss2_kernel<<<NROWS / 256, 256>>>();

    colmean_kernel<<<2, DDIM>>>(z1, z2);
    gproj_kernel<<<2, DDIM>>>(gw1, gb1, ga, gw2, gb2, W);
    sigrows_kernel<<<NROWS / 8, 256>>>(z1, z2);

    finalize_kernel<<<1, 1024>>>(out);
}

// round 5
// speedup vs baseline: 3.2947x; 2.2305x over previous
#include <cuda_runtime.h>
#include <cuda_bf16.h>
#include <math.h>
#include <cstdint>

#define NROWS 4096
#define DDIM  512
#define INV_TAU 5.0f
#define EPS_  1e-15f
#define L2EPS 1e-12f

#define NCHUNK 4
#define CHUNKJ (NROWS / NCHUNK)   // 1024
#define IT 128
#define NIB (NROWS / IT)          // 32

typedef unsigned long long u64;

// ---------------- scratch (static device allocations; no cudaMalloc) ------
__device__ float g_T [NROWS * DDIM];
__device__ float g_h1[NROWS * DDIM];
__device__ float g_h2[NROWS * DDIM];
__device__ __nv_bfloat16 g_a16[NROWS * DDIM];
__device__ __nv_bfloat16 g_b16[NROWS * DDIM];
__device__ float g_rowloss[2 * NROWS];
__device__ float g_gl[4 * NROWS];
__device__ float g_s[2 * DDIM];
__device__ float g_summ[2 * DDIM];
__device__ float g_rp[NCHUNK][4][NROWS];  // row partials: aaS,aaM,abS,abM
__device__ float g_cp[4][NIB][NROWS];     // col partials: abS,abM,bbS,bbM

__device__ __forceinline__ float* scratch_ptr(int sel)
{
    return sel == 0 ? g_T : (sel == 1 ? g_h1 : g_h2);
}

__device__ __forceinline__ uint32_t smem_u32(const void* p) {
    uint32_t a;
    asm("{ .reg .u64 tmp; cvta.to.shared.u64 tmp, %1; cvt.u32.u64 %0, tmp; }"
        : "=r"(a) : "l"(p));
    return a;
}

__device__ __forceinline__ void ldm4(uint32_t* r, uint32_t addr) {
    asm volatile("ldmatrix.sync.aligned.m8n8.x4.shared.b16 {%0,%1,%2,%3}, [%4];"
                 : "=r"(r[0]), "=r"(r[1]), "=r"(r[2]), "=r"(r[3]) : "r"(addr));
}

__device__ __forceinline__ void mma16816(float* c, const uint32_t* a,
                                         uint32_t b0, uint32_t b1) {
    asm volatile("mma.sync.aligned.m16n8k16.row.col.f32.bf16.bf16.f32 "
                 "{%0,%1,%2,%3}, {%4,%5,%6,%7}, {%8,%9}, {%0,%1,%2,%3};"
                 : "+f"(c[0]), "+f"(c[1]), "+f"(c[2]), "+f"(c[3])
                 : "r"(a[0]), "r"(a[1]), "r"(a[2]), "r"(a[3]), "r"(b0), "r"(b1));
}

// ---------------- GEMM: C = A(MxK) * B(NcolsxK)^T + bias, optional PReLU ---
__global__ __launch_bounds__(256) void gemm_abT_kernel(
    const float* __restrict__ Aext, const float* __restrict__ B,
    const float* __restrict__ bias, const float* __restrict__ prelu_a,
    int dst_sel)
{
    const float* A = Aext ? Aext : g_T;
    float* C = scratch_ptr(dst_sel);

    __shared__ float As[32][64];
    __shared__ float Bs[32][64];
    const int I = blockIdx.x * 64;
    const int J = blockIdx.y * 64;
    const int t  = threadIdx.x;
    const int tx = t & 15, ty = t >> 4;
    const int lr = t >> 2;
    const int lk = (t & 3) * 8;
    float c[4][4] = {};
    const float* Ap = A + (size_t)(I + lr) * DDIM + lk;
    const float* Bp = B + (size_t)(J + lr) * DDIM + lk;

    for (int kk = 0; kk < DDIM; kk += 32) {
        float4 a0 = *(const float4*)(Ap + kk);
        float4 a1 = *(const float4*)(Ap + kk + 4);
        float4 b0 = *(const float4*)(Bp + kk);
        float4 b1 = *(const float4*)(Bp + kk + 4);
        As[lk+0][lr]=a0.x; As[lk+1][lr]=a0.y; As[lk+2][lr]=a0.z; As[lk+3][lr]=a0.w;
        As[lk+4][lr]=a1.x; As[lk+5][lr]=a1.y; As[lk+6][lr]=a1.z; As[lk+7][lr]=a1.w;
        Bs[lk+0][lr]=b0.x; Bs[lk+1][lr]=b0.y; Bs[lk+2][lr]=b0.z; Bs[lk+3][lr]=b0.w;
        Bs[lk+4][lr]=b1.x; Bs[lk+5][lr]=b1.y; Bs[lk+6][lr]=b1.z; Bs[lk+7][lr]=b1.w;
        __syncthreads();
        #pragma unroll
        for (int k = 0; k < 32; k++) {
            float4 xv = *(const float4*)&As[k][ty*4];
            float4 yv = *(const float4*)&Bs[k][tx*4];
            float xr[4] = {xv.x, xv.y, xv.z, xv.w};
            float yr[4] = {yv.x, yv.y, yv.z, yv.w};
            #pragma unroll
            for (int r = 0; r < 4; r++)
                #pragma unroll
                for (int cc = 0; cc < 4; cc++)
                    c[r][cc] += xr[r] * yr[cc];
        }
        __syncthreads();
    }

    const bool do_prelu = (prelu_a != nullptr);
    const float pa = do_prelu ? prelu_a[0] : 0.0f;
    #pragma unroll
    for (int r = 0; r < 4; r++) {
        int row = I + ty*4 + r;
        float4 o;
        float* op = &o.x;
        #pragma unroll
        for (int cc = 0; cc < 4; cc++) {
            float v = c[r][cc] + bias[J + tx*4 + cc];
            if (do_prelu) v = (v >= 0.0f) ? v : pa * v;
            op[cc] = v;
        }
        *(float4*)&C[(size_t)row * DDIM + J + tx*4] = o;
    }
}

// ---------------- row L2 normalization -> bf16 --------------------------
__global__ __launch_bounds__(128) void l2norm_kernel()
{
    const float* h = blockIdx.y ? g_h2 : g_h1;
    __nv_bfloat16* o16 = blockIdx.y ? g_b16 : g_a16;
    const int row = blockIdx.x;
    const int t = threadIdx.x;
    float4 v = *(const float4*)&h[(size_t)row * DDIM + t*4];
    float ss = v.x*v.x + v.y*v.y + v.z*v.z + v.w*v.w;
    #pragma unroll
    for (int off = 16; off; off >>= 1) ss += __shfl_down_sync(0xffffffffu, ss, off);
    __shared__ float sm[4];
    __shared__ float stot;
    if ((t & 31) == 0) sm[t >> 5] = ss;
    __syncthreads();
    if (t == 0) stot = sm[0] + sm[1] + sm[2] + sm[3];
    __syncthreads();
    float scale = 1.0f / fmaxf(sqrtf(stot), L2EPS);
    __nv_bfloat162 p0 = __float22bfloat162_rn(make_float2(v.x * scale, v.y * scale));
    __nv_bfloat162 p1 = __float22bfloat162_rn(make_float2(v.z * scale, v.w * scale));
    __nv_bfloat162* dst = (__nv_bfloat162*)&o16[(size_t)row * DDIM + t*4];
    dst[0] = p0;
    dst[1] = p1;
}

// ---------------- HMMA similarity kernel ------------------------------------
// CTA (Ib, c): I-rows Ib*128..+127; streams 16 J-tiles of 64 within chunk c.
// Matrices: aa = a_I.a_J^T, ab = a_I.b_J^T, bb = b_I.b_J^T.
// Row sums (aa, ab) -> g_rp[c]; col sums (ab, bb) -> g_cp[.][Ib].
__global__ __launch_bounds__(256, 1) void sim_kernel(const int* __restrict__ mask)
{
    __shared__ __align__(16) __nv_bfloat16 sAI[128 * 40];
    __shared__ __align__(16) __nv_bfloat16 sBI[128 * 40];
    __shared__ __align__(16) __nv_bfloat16 sAJ[64 * 40];
    __shared__ __align__(16) __nv_bfloat16 sBJ[64 * 40];
    __shared__ float sred[8 * 4 * 64];   // [warp][q][col]

    const int t = threadIdx.x, w = t >> 5, lane = t & 31;
    const int Ib = blockIdx.x, c = blockIdx.y;
    const int I = Ib * IT;

    const uint32_t uAI = smem_u32(sAI), uBI = smem_u32(sBI);
    const uint32_t uAJ = smem_u32(sAJ), uBJ = smem_u32(sBJ);

    const int lr16 = lane & 15, lh = lane >> 4;
    const uint32_t aoff = ((w * 16 + lr16) * 40 + lh * 8) * 2;
    uint32_t boff[4];
    #pragma unroll
    for (int p = 0; p < 4; p++)
        boff[p] = ((p * 16 + lr16) * 40 + lh * 8) * 2;

    // epilogue element mapping
    const int er = lane >> 2;          // row within 16-row block
    const int ec = 2 * (lane & 3);     // col within 8-col block
    const size_t gr0 = (size_t)(I + w * 16 + er);

    float rs_aa0 = 0, rs_aa1 = 0, rm_aa0 = 0, rm_aa1 = 0;
    float rs_ab0 = 0, rs_ab1 = 0, rm_ab0 = 0, rm_ab1 = 0;

    for (int jt = 0; jt < 16; jt++) {
        const int J0 = c * CHUNKJ + jt * 64;
        float acc[3][8][4];
        #pragma unroll
        for (int m = 0; m < 3; m++)
            #pragma unroll
            for (int nb = 0; nb < 8; nb++)
                #pragma unroll
                for (int q = 0; q < 4; q++) acc[m][nb][q] = 0.0f;

        for (int ck = 0; ck < 16; ck++) {   // 16 k-slabs of 32
            __syncthreads();
            // store slab to smem
            #pragma unroll
            for (int it2 = 0; it2 < 2; it2++) {
                int idx = t + it2 * 256;
                int row = idx >> 2, qd = idx & 3;
                *(uint4*)(sAI + row * 40 + qd * 8) =
                    *(const uint4*)(g_a16 + (size_t)(I + row) * DDIM + ck * 32 + qd * 8);
                *(uint4*)(sBI + row * 40 + qd * 8) =
                    *(const uint4*)(g_b16 + (size_t)(I + row) * DDIM + ck * 32 + qd * 8);
            }
            {
                int row = t >> 2, qd = t & 3;
                *(uint4*)(sAJ + row * 40 + qd * 8) =
                    *(const uint4*)(g_a16 + (size_t)(J0 + row) * DDIM + ck * 32 + qd * 8);
                *(uint4*)(sBJ + row * 40 + qd * 8) =
                    *(const uint4*)(g_b16 + (size_t)(J0 + row) * DDIM + ck * 32 + qd * 8);
            }
            __syncthreads();

            #pragma unroll
            for (int ks = 0; ks < 2; ks++) {
                uint32_t fA[4], fB[4], fAJ[4][4], fBJ[4][4];
                ldm4(fA, uAI + aoff + ks * 32);
                ldm4(fB, uBI + aoff + ks * 32);
                #pragma unroll
                for (int p = 0; p < 4; p++) {
                    ldm4(fAJ[p], uAJ + boff[p] + ks * 32);
                    ldm4(fBJ[p], uBJ + boff[p] + ks * 32);
                }
                #pragma unroll
                for (int p = 0; p < 4; p++) {
                    mma16816(acc[0][2*p],   fA, fAJ[p][0], fAJ[p][2]);
                    mma16816(acc[0][2*p+1], fA, fAJ[p][1], fAJ[p][3]);
                    mma16816(acc[1][2*p],   fA, fBJ[p][0], fBJ[p][2]);
                    mma16816(acc[1][2*p+1], fA, fBJ[p][1], fBJ[p][3]);
                    mma16816(acc[2][2*p],   fB, fBJ[p][0], fBJ[p][2]);
                    mma16816(acc[2][2*p+1], fB, fBJ[p][1], fBJ[p][3]);
                }
            }
        }

        // ---- epilogue for this J-tile ----
        __syncthreads();   // mainloop smem reads done; sred free
        #pragma unroll
        for (int nb = 0; nb < 8; nb++) {
            const int gc = J0 + nb * 8 + ec;
            int2 m0 = *(const int2*)(mask + gr0 * NROWS + gc);
            int2 m1 = *(const int2*)(mask + (gr0 + 8) * NROWS + gc);
            float m00 = (float)m0.x, m01 = (float)m0.y;
            float m10 = (float)m1.x, m11 = (float)m1.y;

            float ea0 = __expf(acc[0][nb][0] * INV_TAU);
            float ea1 = __expf(acc[0][nb][1] * INV_TAU);
            float ea2 = __expf(acc[0][nb][2] * INV_TAU);
            float ea3 = __expf(acc[0][nb][3] * INV_TAU);
            float eb0 = __expf(acc[1][nb][0] * INV_TAU);
            float eb1 = __expf(acc[1][nb][1] * INV_TAU);
            float eb2 = __expf(acc[1][nb][2] * INV_TAU);
            float eb3 = __expf(acc[1][nb][3] * INV_TAU);
            float ec0 = __expf(acc[2][nb][0] * INV_TAU);
            float ec1 = __expf(acc[2][nb][1] * INV_TAU);
            float ec2 = __expf(acc[2][nb][2] * INV_TAU);
            float ec3 = __expf(acc[2][nb][3] * INV_TAU);

            rs_aa0 += ea0 + ea1;  rm_aa0 += ea0 * m00 + ea1 * m01;
            rs_aa1 += ea2 + ea3;  rm_aa1 += ea2 * m10 + ea3 * m11;
            rs_ab0 += eb0 + eb1;  rm_ab0 += eb0 * m00 + eb1 * m01;
            rs_ab1 += eb2 + eb3;  rm_ab1 += eb2 * m10 + eb3 * m11;

            float v[8];
            v[0] = eb0 + eb2;              v[1] = eb1 + eb3;               // abS
            v[2] = eb0 * m00 + eb2 * m10;  v[3] = eb1 * m01 + eb3 * m11;   // abM
            v[4] = ec0 + ec2;              v[5] = ec1 + ec3;               // bbS
            v[6] = ec0 * m00 + ec2 * m10;  v[7] = ec1 * m01 + ec3 * m11;   // bbM
            #pragma unroll
            for (int q = 0; q < 8; q++) {
                v[q] += __shfl_down_sync(0xffffffffu, v[q], 16);
                v[q] += __shfl_down_sync(0xffffffffu, v[q], 8);
                v[q] += __shfl_down_sync(0xffffffffu, v[q], 4);
            }
            if (lane < 4) {
                int col = nb * 8 + 2 * lane;
                sred[(w * 4 + 0) * 64 + col]     = v[0];
                sred[(w * 4 + 0) * 64 + col + 1] = v[1];
                sred[(w * 4 + 1) * 64 + col]     = v[2];
                sred[(w * 4 + 1) * 64 + col + 1] = v[3];
                sred[(w * 4 + 2) * 64 + col]     = v[4];
                sred[(w * 4 + 2) * 64 + col + 1] = v[5];
                sred[(w * 4 + 3) * 64 + col]     = v[6];
                sred[(w * 4 + 3) * 64 + col + 1] = v[7];
            }
        }
        __syncthreads();
        {
            int q = t >> 6, col = t & 63;
            float s = 0.0f;
            #pragma unroll
            for (int ww = 0; ww < 8; ww++)
                s += sred[(ww * 4 + q) * 64 + col];
            g_cp[q][Ib][J0 + col] = s;
        }
    }

    // ---- final row-partial write ----
    #pragma unroll
    for (int d = 1; d < 4; d <<= 1) {
        rs_aa0 += __shfl_down_sync(0xffffffffu, rs_aa0, d, 4);
        rs_aa1 += __shfl_down_sync(0xffffffffu, rs_aa1, d, 4);
        rm_aa0 += __shfl_down_sync(0xffffffffu, rm_aa0, d, 4);
        rm_aa1 += __shfl_down_sync(0xffffffffu, rm_aa1, d, 4);
        rs_ab0 += __shfl_down_sync(0xffffffffu, rs_ab0, d, 4);
        rs_ab1 += __shfl_down_sync(0xffffffffu, rs_ab1, d, 4);
        rm_ab0 += __shfl_down_sync(0xffffffffu, rm_ab0, d, 4);
        rm_ab1 += __shfl_down_sync(0xffffffffu, rm_ab1, d, 4);
    }
    if ((lane & 3) == 0) {
        int r0 = I + w * 16 + (lane >> 2);
        g_rp[c][0][r0]     = rs_aa0;
        g_rp[c][0][r0 + 8] = rs_aa1;
        g_rp[c][1][r0]     = rm_aa0;
        g_rp[c][1][r0 + 8] = rm_aa1;
        g_rp[c][2][r0]     = rs_ab0;
        g_rp[c][2][r0 + 8] = rs_ab1;
        g_rp[c][3][r0]     = rm_ab0;
        g_rp[c][3][r0 + 8] = rm_ab1;
    }
}

// ---------------- combine partials -> per-row losses ------------------------
__global__ __launch_bounds__(256) void rowloss2_kernel()
{
    int i = blockIdx.x * 256 + threadIdx.x;
    float aas = 0, aam = 0, abs_ = 0, abm = 0;
    #pragma unroll
    for (int c = 0; c < NCHUNK; c++) {
        aas  += g_rp[c][0][i];
        aam  += g_rp[c][1][i];
        abs_ += g_rp[c][2][i];
        abm  += g_rp[c][3][i];
    }
    float cabs = 0, cabm = 0, cbbs = 0, cbbm = 0;
    for (int b = 0; b < NIB; b++) {
        cabs += g_cp[0][b][i];
        cabm += g_cp[1][b][i];
        cbbs += g_cp[2][b][i];
        cbbm += g_cp[3][b][i];
    }
    // pass0: infonce(h1,h2,m) row i
    g_rowloss[i]         = -logf(abm / (aas + abs_ - aam));
    // pass1: infonce(h2,h1,m.T) row i (via column sums)
    g_rowloss[NROWS + i] = -logf(cabm / (cbbs + cabs - cbbm));
}

// ---------------- column means of z1, z2 (readout s) -----------------------
__global__ __launch_bounds__(512) void colmean_kernel(const float* __restrict__ z1,
                                                      const float* __restrict__ z2)
{
    const float* z = blockIdx.x ? z2 : z1;
    const int t = threadIdx.x;
    float a0 = 0, a1 = 0, a2 = 0, a3 = 0;
    for (int r = 0; r < NROWS; r += 4) {
        a0 += z[(size_t)(r+0) * DDIM + t];
        a1 += z[(size_t)(r+1) * DDIM + t];
        a2 += z[(size_t)(r+2) * DDIM + t];
        a3 += z[(size_t)(r+3) * DDIM + t];
    }
    g_s[blockIdx.x * DDIM + t] = (a0 + a1 + a2 + a3) * (1.0f / NROWS);
}

// ---------------- global projector chain: summ_p = W @ proj(s_p) -----------
__device__ __forceinline__ void mv_stage(const float* __restrict__ Wm,
                                         const float* __restrict__ bias,
                                         const float* vin, float* vout,
                                         float pa, bool prelu_on,
                                         int warp, int lane)
{
    for (int rr = 0; rr < 32; rr++) {
        int o = warp * 32 + rr;
        const float* wr = Wm + (size_t)o * DDIM;
        float acc = 0.0f;
        for (int i = lane; i < DDIM; i += 32) acc += wr[i] * vin[i];
        #pragma unroll
        for (int off = 16; off; off >>= 1) acc += __shfl_down_sync(0xffffffffu, acc, off);
        if (lane == 0) {
            float v = acc + (bias ? bias[o] : 0.0f);
            if (prelu_on) v = (v >= 0.0f) ? v : pa * v;
            vout[o] = v;
        }
    }
}

__global__ __launch_bounds__(512) void gproj_kernel(
    const float* __restrict__ gw1, const float* __restrict__ gb1,
    const float* __restrict__ ga,  const float* __restrict__ gw2,
    const float* __restrict__ gb2, const float* __restrict__ W)
{
    __shared__ float v[DDIM], u[DDIM], hh[DDIM];
    const int p = blockIdx.x;
    const int t = threadIdx.x, warp = t >> 5, lane = t & 31;
    v[t] = g_s[p * DDIM + t];
    __syncthreads();
    mv_stage(gw1, gb1, v, u, ga[0], true, warp, lane);
    __syncthreads();
    mv_stage(gw2, gb2, u, hh, 0.0f, false, warp, lane);
    __syncthreads();
    for (int rr = 0; rr < 32; rr++) {
        int o = warp * 32 + rr;
        const float* wr = W + (size_t)o * DDIM;
        float acc = 0.0f;
        for (int i = lane; i < DDIM; i += 32) acc += wr[i] * hh[i];
        #pragma unroll
        for (int off = 16; off; off >>= 1) acc += __shfl_down_sync(0xffffffffu, acc, off);
        if (lane == 0) g_summ[p * DDIM + o] = acc;
    }
}

// ---------------- per-row discriminator terms ------------------------------
__global__ __launch_bounds__(256) void sigrows_kernel(const float* __restrict__ z1,
                                                      const float* __restrict__ z2)
{
    const int warp = threadIdx.x >> 5, lane = threadIdx.x & 31;
    const int row = blockIdx.x * 8 + warp;
    const float* r1 = z1 + (size_t)row * DDIM;
    const float* r2 = z2 + (size_t)row * DDIM;
    float d11 = 0, d12 = 0, d21 = 0, d22 = 0;
    for (int i = lane; i < DDIM; i += 32) {
        float a = r1[i], b = r2[i];
        float s1 = g_summ[i], s2 = g_summ[DDIM + i];
        d11 += a * s1; d12 += a * s2; d21 += b * s1; d22 += b * s2;
    }
    #pragma unroll
    for (int off = 16; off; off >>= 1) {
        d11 += __shfl_down_sync(0xffffffffu, d11, off);
        d12 += __shfl_down_sync(0xffffffffu, d12, off);
        d21 += __shfl_down_sync(0xffffffffu, d21, off);
        d22 += __shfl_down_sync(0xffffffffu, d22, off);
    }
    if (lane == 0) {
        float sg11 = 1.0f / (1.0f + expf(-d11));
        float sg21 = 1.0f / (1.0f + expf(-d21));
        float sg22 = 1.0f / (1.0f + expf(-d22));
        float sg12 = 1.0f / (1.0f + expf(-d12));
        g_gl[0 * NROWS + row] = -logf(sg11 + EPS_);
        g_gl[1 * NROWS + row] = -logf(1.0f - sg21 + EPS_);
        g_gl[2 * NROWS + row] = -logf(sg22 + EPS_);
        g_gl[3 * NROWS + row] = -logf(1.0f - sg12 + EPS_);
    }
}

// ---------------- final deterministic reduction ----------------------------
__global__ __launch_bounds__(1024) void finalize_kernel(float* __restrict__ out)
{
    __shared__ float red[32];
    float acc[6] = {0, 0, 0, 0, 0, 0};
    for (int i = threadIdx.x; i < NROWS; i += 1024) {
        acc[0] += g_rowloss[i];
        acc[1] += g_rowloss[NROWS + i];
        acc[2] += g_gl[i];
        acc[3] += g_gl[NROWS + i];
        acc[4] += g_gl[2 * NROWS + i];
        acc[5] += g_gl[3 * NROWS + i];
    }
    const int lane = threadIdx.x & 31, warp = threadIdx.x >> 5;
    float tot[6];
    for (int q = 0; q < 6; q++) {
        float v = acc[q];
        #pragma unroll
        for (int off = 16; off; off >>= 1) v += __shfl_down_sync(0xffffffffu, v, off);
        if (lane == 0) red[warp] = v;
        __syncthreads();
        if (warp == 0) {
            float w = red[lane];
            #pragma unroll
            for (int off = 16; off; off >>= 1) w += __shfl_down_sync(0xffffffffu, w, off);
            if (lane == 0) tot[q] = w;
        }
        __syncthreads();
    }
    if (threadIdx.x == 0) {
        const float inv = 1.0f / NROWS;
        float local = 0.5f * (tot[0] + tot[1]) * inv;
        float gl1   = 0.5f * (tot[2] + tot[3]) * inv;
        float gl2   = 0.5f * (tot[4] + tot[5]) * inv;
        float glob  = 0.5f * (gl1 + gl2);
        out[0] = 0.5f * local + 0.5f * glob;   // ALPHA = 0.5
    }
}

// ---------------- launch ----------------------------------------------------
extern "C" void kernel_launch(void* const* d_in, const int* in_sizes, int n_in,
                              void* d_out, int out_size)
{
    const float* z1  = (const float*)d_in[0];
    const float* z2  = (const float*)d_in[1];
    const float* lw1 = (const float*)d_in[2];
    const float* lb1 = (const float*)d_in[3];
    const float* la  = (const float*)d_in[4];
    const float* lw2 = (const float*)d_in[5];
    const float* lb2 = (const float*)d_in[6];
    const float* gw1 = (const float*)d_in[7];
    const float* gb1 = (const float*)d_in[8];
    const float* ga  = (const float*)d_in[9];
    const float* gw2 = (const float*)d_in[10];
    const float* gb2 = (const float*)d_in[11];
    const float* W   = (const float*)d_in[12];
    const int*   mask= (const int*)  d_in[13];
    float* out = (float*)d_out;

    dim3 gemm_grid(NROWS / 64, DDIM / 64);

    gemm_abT_kernel<<<gemm_grid, 256>>>(z1,      lw1, lb1, la,      0);
    gemm_abT_kernel<<<gemm_grid, 256>>>(nullptr, lw2, lb2, nullptr, 1);
    gemm_abT_kernel<<<gemm_grid, 256>>>(z2,      lw1, lb1, la,      0);
    gemm_abT_kernel<<<gemm_grid, 256>>>(nullptr, lw2, lb2, nullptr, 2);

    l2norm_kernel<<<dim3(NROWS, 2), 128>>>();

    sim_kernel<<<dim3(NIB, NCHUNK), 256>>>(mask);
    rowloss2_kernel<<<NROWS / 256, 256>>>();

    colmean_kernel<<<2, DDIM>>>(z1, z2);
    gproj_kernel<<<2, DDIM>>>(gw1, gb1, ga, gw2, gb2, W);
    sigrows_kernel<<<NROWS / 8, 256>>>(z1, z2);

    finalize_kernel<<<1, 1024>>>(out);
}

// round 6
// speedup vs baseline: 4.8774x; 1.4803x over previous
#include <cuda_runtime.h>
#include <cuda_bf16.h>
#include <math.h>
#include <cstdint>

#define NROWS 4096
#define DDIM  512
#define INV_TAU 5.0f
#define EPS_  1e-15f
#define L2EPS 1e-12f

#define NCHUNK 4
#define CHUNKJ (NROWS / NCHUNK)   // 1024
#define IT 128
#define NIB (NROWS / IT)          // 32

// sim kernel dynamic smem: 2 buffers x 30720B + 8192B sred
#define SIMBUF_BYTES 30720
#define SIM_SMEM_BYTES (2 * SIMBUF_BYTES + 8192)

typedef unsigned long long u64;

// ---------------- scratch (static device allocations; no cudaMalloc) ------
__device__ float g_h1[NROWS * DDIM];
__device__ float g_h2[NROWS * DDIM];
__device__ __nv_bfloat16 g_z16a[NROWS * DDIM];
__device__ __nv_bfloat16 g_z16b[NROWS * DDIM];
__device__ __nv_bfloat16 g_T16a[NROWS * DDIM];
__device__ __nv_bfloat16 g_T16b[NROWS * DDIM];
__device__ __nv_bfloat16 g_w1s[DDIM * DDIM];
__device__ __nv_bfloat16 g_w2s[DDIM * DDIM];
__device__ __nv_bfloat16 g_a16[NROWS * DDIM];
__device__ __nv_bfloat16 g_b16[NROWS * DDIM];
__device__ float g_rowloss[2 * NROWS];
__device__ float g_gl[4 * NROWS];
__device__ float g_s[2 * DDIM];
__device__ float g_summ[2 * DDIM];
__device__ float g_rp[NCHUNK][4][NROWS];  // row partials: aaS,aaM,abS,abM
__device__ float g_cp[4][NIB][NROWS];     // col partials: abS,abM,bbS,bbM

// ---------------- PTX helpers ----------------------------------------------
__device__ __forceinline__ uint32_t smem_u32(const void* p) {
    uint32_t a;
    asm("{ .reg .u64 tmp; cvta.to.shared.u64 tmp, %1; cvt.u32.u64 %0, tmp; }"
        : "=r"(a) : "l"(p));
    return a;
}

__device__ __forceinline__ void ldm4(uint32_t* r, uint32_t addr) {
    asm volatile("ldmatrix.sync.aligned.m8n8.x4.shared.b16 {%0,%1,%2,%3}, [%4];"
                 : "=r"(r[0]), "=r"(r[1]), "=r"(r[2]), "=r"(r[3]) : "r"(addr));
}

__device__ __forceinline__ void mma16816(float* c, const uint32_t* a,
                                         uint32_t b0, uint32_t b1) {
    asm volatile("mma.sync.aligned.m16n8k16.row.col.f32.bf16.bf16.f32 "
                 "{%0,%1,%2,%3}, {%4,%5,%6,%7}, {%8,%9}, {%0,%1,%2,%3};"
                 : "+f"(c[0]), "+f"(c[1]), "+f"(c[2]), "+f"(c[3])
                 : "r"(a[0]), "r"(a[1]), "r"(a[2]), "r"(a[3]), "r"(b0), "r"(b1));
}

__device__ __forceinline__ void cpa16(uint32_t dst, const void* src) {
    asm volatile("cp.async.cg.shared.global [%0], [%1], 16;"
                 :: "r"(dst), "l"(src) : "memory");
}
#define CP_COMMIT() asm volatile("cp.async.commit_group;" ::: "memory")
template <int N>
__device__ __forceinline__ void cp_wait() {
    asm volatile("cp.async.wait_group %0;" :: "n"(N) : "memory");
}

// ---------------- fp32 -> bf16 conversion -----------------------------------
__global__ __launch_bounds__(256) void conv_bf16_kernel(const float* __restrict__ src,
                                                        int dst_sel, int n4)
{
    int i = blockIdx.x * 256 + threadIdx.x;
    if (i >= n4) return;
    __nv_bfloat16* dst = dst_sel == 0 ? g_z16a : dst_sel == 1 ? g_z16b
                       : dst_sel == 2 ? g_w1s  : g_w2s;
    float4 v = ((const float4*)src)[i];
    __nv_bfloat162* d = (__nv_bfloat162*)(dst + (size_t)i * 4);
    d[0] = __float22bfloat162_rn(make_float2(v.x, v.y));
    d[1] = __float22bfloat162_rn(make_float2(v.z, v.w));
}

// ---------------- HMMA projector GEMM ---------------------------------------
// C[4096,512] = A[4096,512] @ W[512,512]^T + bias (optional PReLU).
// stage 1: A = g_z16{a,b}, W = g_w1s, out = g_T16{a,b} (bf16)
// stage 2: A = g_T16{a,b}, W = g_w2s, out = g_h{1,2} (fp32)
__global__ __launch_bounds__(256, 1) void gemm_hmma_kernel(
    const float* __restrict__ bias, const float* __restrict__ prelu_a, int stage)
{
    __shared__ __align__(16) __nv_bfloat16 sA[2][128 * 40];
    __shared__ __align__(16) __nv_bfloat16 sW[2][128 * 40];

    const int t = threadIdx.x, w = t >> 5, lane = t & 31;
    const int I0 = blockIdx.x * 128, J0 = blockIdx.y * 128;
    const int z = blockIdx.z;

    const __nv_bfloat16* __restrict__ A =
        (stage == 1) ? (z ? g_z16b : g_z16a) : (z ? g_T16b : g_T16a);
    const __nv_bfloat16* __restrict__ Wm = (stage == 1) ? g_w1s : g_w2s;

    const uint32_t uA0 = smem_u32(sA[0]), uA1 = smem_u32(sA[1]);
    const uint32_t uW0 = smem_u32(sW[0]), uW1 = smem_u32(sW[1]);

    const int lr16 = lane & 15, lh = lane >> 4;
    const uint32_t aoff = ((w * 16 + lr16) * 40 + lh * 8) * 2;
    uint32_t boff[8];
    #pragma unroll
    for (int p = 0; p < 8; p++)
        boff[p] = ((p * 16 + lr16) * 40 + lh * 8) * 2;

    // cp.async indices: 2 ops per thread per array
    const int r0 = t >> 2, q0 = (t & 3);
    const int r1 = (t + 256) >> 2, q1 = ((t + 256) & 3);
    const uint32_t d0 = (r0 * 40 + q0 * 8) * 2;
    const uint32_t d1 = (r1 * 40 + q1 * 8) * 2;

    float acc[8][2][4];
    #pragma unroll
    for (int p = 0; p < 8; p++)
        #pragma unroll
        for (int h = 0; h < 2; h++)
            #pragma unroll
            for (int q = 0; q < 4; q++) acc[p][h][q] = 0.0f;

    // prologue: slab 0
    {
        cpa16(uA0 + d0, A + (size_t)(I0 + r0) * DDIM + q0 * 8);
        cpa16(uA0 + d1, A + (size_t)(I0 + r1) * DDIM + q1 * 8);
        cpa16(uW0 + d0, Wm + (size_t)(J0 + r0) * DDIM + q0 * 8);
        cpa16(uW0 + d1, Wm + (size_t)(J0 + r1) * DDIM + q1 * 8);
        CP_COMMIT();
    }

    for (int ck = 0; ck < 16; ck++) {
        const uint32_t uAc = (ck & 1) ? uA1 : uA0;
        const uint32_t uWc = (ck & 1) ? uW1 : uW0;
        if (ck < 15) {
            const uint32_t uAn = (ck & 1) ? uA0 : uA1;
            const uint32_t uWn = (ck & 1) ? uW0 : uW1;
            const int kb = (ck + 1) * 32;
            cpa16(uAn + d0, A + (size_t)(I0 + r0) * DDIM + kb + q0 * 8);
            cpa16(uAn + d1, A + (size_t)(I0 + r1) * DDIM + kb + q1 * 8);
            cpa16(uWn + d0, Wm + (size_t)(J0 + r0) * DDIM + kb + q0 * 8);
            cpa16(uWn + d1, Wm + (size_t)(J0 + r1) * DDIM + kb + q1 * 8);
            CP_COMMIT();
            cp_wait<1>();
        } else {
            cp_wait<0>();
        }
        __syncthreads();
        #pragma unroll
        for (int ks = 0; ks < 2; ks++) {
            uint32_t fA[4];
            ldm4(fA, uAc + aoff + ks * 32);
            #pragma unroll
            for (int p = 0; p < 8; p++) {
                uint32_t fW[4];
                ldm4(fW, uWc + boff[p] + ks * 32);
                mma16816(acc[p][0], fA, fW[0], fW[2]);
                mma16816(acc[p][1], fA, fW[1], fW[3]);
            }
        }
        __syncthreads();
    }

    // epilogue
    const int er = lane >> 2, ec = 2 * (lane & 3);
    const int row = I0 + w * 16 + er;
    const bool do_prelu = (prelu_a != nullptr);
    const float pa = do_prelu ? prelu_a[0] : 0.0f;

    __nv_bfloat16* Tout = z ? g_T16b : g_T16a;
    float* Hout = z ? g_h2 : g_h1;

    #pragma unroll
    for (int p = 0; p < 8; p++) {
        #pragma unroll
        for (int h = 0; h < 2; h++) {
            int col = J0 + p * 16 + h * 8 + ec;
            float b0 = bias[col], b1 = bias[col + 1];
            float v0 = acc[p][h][0] + b0, v1 = acc[p][h][1] + b1;
            float v2 = acc[p][h][2] + b0, v3 = acc[p][h][3] + b1;
            if (do_prelu) {
                v0 = (v0 >= 0.0f) ? v0 : pa * v0;
                v1 = (v1 >= 0.0f) ? v1 : pa * v1;
                v2 = (v2 >= 0.0f) ? v2 : pa * v2;
                v3 = (v3 >= 0.0f) ? v3 : pa * v3;
            }
            if (stage == 1) {
                *(__nv_bfloat162*)(Tout + (size_t)row * DDIM + col) =
                    __float22bfloat162_rn(make_float2(v0, v1));
                *(__nv_bfloat162*)(Tout + (size_t)(row + 8) * DDIM + col) =
                    __float22bfloat162_rn(make_float2(v2, v3));
            } else {
                *(float2*)(Hout + (size_t)row * DDIM + col) = make_float2(v0, v1);
                *(float2*)(Hout + (size_t)(row + 8) * DDIM + col) = make_float2(v2, v3);
            }
        }
    }
}

// ---------------- row L2 normalization -> bf16 --------------------------
__global__ __launch_bounds__(128) void l2norm_kernel()
{
    const float* h = blockIdx.y ? g_h2 : g_h1;
    __nv_bfloat16* o16 = blockIdx.y ? g_b16 : g_a16;
    const int row = blockIdx.x;
    const int t = threadIdx.x;
    float4 v = *(const float4*)&h[(size_t)row * DDIM + t*4];
    float ss = v.x*v.x + v.y*v.y + v.z*v.z + v.w*v.w;
    #pragma unroll
    for (int off = 16; off; off >>= 1) ss += __shfl_down_sync(0xffffffffu, ss, off);
    __shared__ float sm[4];
    __shared__ float stot;
    if ((t & 31) == 0) sm[t >> 5] = ss;
    __syncthreads();
    if (t == 0) stot = sm[0] + sm[1] + sm[2] + sm[3];
    __syncthreads();
    float scale = 1.0f / fmaxf(sqrtf(stot), L2EPS);
    __nv_bfloat162 p0 = __float22bfloat162_rn(make_float2(v.x * scale, v.y * scale));
    __nv_bfloat162 p1 = __float22bfloat162_rn(make_float2(v.z * scale, v.w * scale));
    __nv_bfloat162* dst = (__nv_bfloat162*)&o16[(size_t)row * DDIM + t*4];
    dst[0] = p0;
    dst[1] = p1;
}

// ---------------- HMMA similarity kernel (cp.async double-buffered) ---------
// CTA (Ib, c): I-rows Ib*128..+127; streams 16 J-tiles of 64 within chunk c.
// aa = a_I.a_J^T, ab = a_I.b_J^T, bb = b_I.b_J^T.
// Row sums (aa, ab) -> g_rp[c]; col sums (ab, bb) -> g_cp[.][Ib].
// Buffer layout (bytes): AI@0 (10240), BI@10240, AJ@20480 (5120), BJ@25600.
__global__ __launch_bounds__(256, 1) void sim_kernel(const int* __restrict__ mask)
{
    extern __shared__ __align__(16) char dsm[];
    const uint32_t u0 = smem_u32(dsm);
    float* sred = (float*)(dsm + 2 * SIMBUF_BYTES);   // 2048 floats

    const int t = threadIdx.x, w = t >> 5, lane = t & 31;
    const int Ib = blockIdx.x, c = blockIdx.y;
    const int I = Ib * IT;

    const int lr16 = lane & 15, lh = lane >> 4;
    const uint32_t aoff = ((w * 16 + lr16) * 40 + lh * 8) * 2;
    uint32_t boff[4];
    #pragma unroll
    for (int p = 0; p < 4; p++)
        boff[p] = ((p * 16 + lr16) * 40 + lh * 8) * 2;

    // cp.async indices
    const int rI0 = t >> 2, qI0 = t & 3;
    const int rI1 = (t + 256) >> 2, qI1 = (t + 256) & 3;
    const uint32_t dI0 = (rI0 * 40 + qI0 * 8) * 2;
    const uint32_t dI1 = (rI1 * 40 + qI1 * 8) * 2;

    const int er = lane >> 2;
    const int ec = 2 * (lane & 3);
    const size_t gr0 = (size_t)(I + w * 16 + er);

    float rs_aa0 = 0, rs_aa1 = 0, rm_aa0 = 0, rm_aa1 = 0;
    float rs_ab0 = 0, rs_ab1 = 0, rm_ab0 = 0, rm_ab1 = 0;

    for (int jt = 0; jt < 16; jt++) {
        const int J0 = c * CHUNKJ + jt * 64;
        float acc[3][8][4];
        #pragma unroll
        for (int m = 0; m < 3; m++)
            #pragma unroll
            for (int nb = 0; nb < 8; nb++)
                #pragma unroll
                for (int q = 0; q < 4; q++) acc[m][nb][q] = 0.0f;

        // prologue: slab 0 into buf0
        {
            const uint32_t b = u0;
            cpa16(b + dI0, g_a16 + (size_t)(I + rI0) * DDIM + qI0 * 8);
            cpa16(b + dI1, g_a16 + (size_t)(I + rI1) * DDIM + qI1 * 8);
            cpa16(b + 10240 + dI0, g_b16 + (size_t)(I + rI0) * DDIM + qI0 * 8);
            cpa16(b + 10240 + dI1, g_b16 + (size_t)(I + rI1) * DDIM + qI1 * 8);
            cpa16(b + 20480 + dI0, g_a16 + (size_t)(J0 + rI0) * DDIM + qI0 * 8);
            cpa16(b + 25600 + dI0, g_b16 + (size_t)(J0 + rI0) * DDIM + qI0 * 8);
            CP_COMMIT();
        }

        for (int ck = 0; ck < 16; ck++) {
            const uint32_t bc = u0 + (ck & 1) * SIMBUF_BYTES;
            if (ck < 15) {
                const uint32_t bn = u0 + ((ck + 1) & 1) * SIMBUF_BYTES;
                const int kb = (ck + 1) * 32;
                cpa16(bn + dI0, g_a16 + (size_t)(I + rI0) * DDIM + kb + qI0 * 8);
                cpa16(bn + dI1, g_a16 + (size_t)(I + rI1) * DDIM + kb + qI1 * 8);
                cpa16(bn + 10240 + dI0, g_b16 + (size_t)(I + rI0) * DDIM + kb + qI0 * 8);
                cpa16(bn + 10240 + dI1, g_b16 + (size_t)(I + rI1) * DDIM + kb + qI1 * 8);
                cpa16(bn + 20480 + dI0, g_a16 + (size_t)(J0 + rI0) * DDIM + kb + qI0 * 8);
                cpa16(bn + 25600 + dI0, g_b16 + (size_t)(J0 + rI0) * DDIM + kb + qI0 * 8);
                CP_COMMIT();
                cp_wait<1>();
            } else {
                cp_wait<0>();
            }
            __syncthreads();

            const uint32_t uAI = bc, uBI = bc + 10240;
            const uint32_t uAJ = bc + 20480, uBJ = bc + 25600;
            #pragma unroll
            for (int ks = 0; ks < 2; ks++) {
                uint32_t fA[4], fB[4], fAJ[4][4], fBJ[4][4];
                ldm4(fA, uAI + aoff + ks * 32);
                ldm4(fB, uBI + aoff + ks * 32);
                #pragma unroll
                for (int p = 0; p < 4; p++) {
                    ldm4(fAJ[p], uAJ + boff[p] + ks * 32);
                    ldm4(fBJ[p], uBJ + boff[p] + ks * 32);
                }
                #pragma unroll
                for (int p = 0; p < 4; p++) {
                    mma16816(acc[0][2*p],   fA, fAJ[p][0], fAJ[p][2]);
                    mma16816(acc[0][2*p+1], fA, fAJ[p][1], fAJ[p][3]);
                    mma16816(acc[1][2*p],   fA, fBJ[p][0], fBJ[p][2]);
                    mma16816(acc[1][2*p+1], fA, fBJ[p][1], fBJ[p][3]);
                    mma16816(acc[2][2*p],   fB, fBJ[p][0], fBJ[p][2]);
                    mma16816(acc[2][2*p+1], fB, fBJ[p][1], fBJ[p][3]);
                }
            }
            __syncthreads();
        }

        // ---- epilogue for this J-tile ----
        #pragma unroll
        for (int nb = 0; nb < 8; nb++) {
            const int gc = J0 + nb * 8 + ec;
            int2 m0 = *(const int2*)(mask + gr0 * NROWS + gc);
            int2 m1 = *(const int2*)(mask + (gr0 + 8) * NROWS + gc);
            float m00 = (float)m0.x, m01 = (float)m0.y;
            float m10 = (float)m1.x, m11 = (float)m1.y;

            float ea0 = __expf(acc[0][nb][0] * INV_TAU);
            float ea1 = __expf(acc[0][nb][1] * INV_TAU);
            float ea2 = __expf(acc[0][nb][2] * INV_TAU);
            float ea3 = __expf(acc[0][nb][3] * INV_TAU);
            float eb0 = __expf(acc[1][nb][0] * INV_TAU);
            float eb1 = __expf(acc[1][nb][1] * INV_TAU);
            float eb2 = __expf(acc[1][nb][2] * INV_TAU);
            float eb3 = __expf(acc[1][nb][3] * INV_TAU);
            float ec0 = __expf(acc[2][nb][0] * INV_TAU);
            float ec1 = __expf(acc[2][nb][1] * INV_TAU);
            float ec2 = __expf(acc[2][nb][2] * INV_TAU);
            float ec3 = __expf(acc[2][nb][3] * INV_TAU);

            rs_aa0 += ea0 + ea1;  rm_aa0 += ea0 * m00 + ea1 * m01;
            rs_aa1 += ea2 + ea3;  rm_aa1 += ea2 * m10 + ea3 * m11;
            rs_ab0 += eb0 + eb1;  rm_ab0 += eb0 * m00 + eb1 * m01;
            rs_ab1 += eb2 + eb3;  rm_ab1 += eb2 * m10 + eb3 * m11;

            float v[8];
            v[0] = eb0 + eb2;              v[1] = eb1 + eb3;               // abS
            v[2] = eb0 * m00 + eb2 * m10;  v[3] = eb1 * m01 + eb3 * m11;   // abM
            v[4] = ec0 + ec2;              v[5] = ec1 + ec3;               // bbS
            v[6] = ec0 * m00 + ec2 * m10;  v[7] = ec1 * m01 + ec3 * m11;   // bbM
            #pragma unroll
            for (int q = 0; q < 8; q++) {
                v[q] += __shfl_down_sync(0xffffffffu, v[q], 16);
                v[q] += __shfl_down_sync(0xffffffffu, v[q], 8);
                v[q] += __shfl_down_sync(0xffffffffu, v[q], 4);
            }
            if (lane < 4) {
                int col = nb * 8 + 2 * lane;
                sred[(w * 4 + 0) * 64 + col]     = v[0];
                sred[(w * 4 + 0) * 64 + col + 1] = v[1];
                sred[(w * 4 + 1) * 64 + col]     = v[2];
                sred[(w * 4 + 1) * 64 + col + 1] = v[3];
                sred[(w * 4 + 2) * 64 + col]     = v[4];
                sred[(w * 4 + 2) * 64 + col + 1] = v[5];
                sred[(w * 4 + 3) * 64 + col]     = v[6];
                sred[(w * 4 + 3) * 64 + col + 1] = v[7];
            }
        }
        __syncthreads();
        {
            int q = t >> 6, col = t & 63;
            float s = 0.0f;
            #pragma unroll
            for (int ww = 0; ww < 8; ww++)
                s += sred[(ww * 4 + q) * 64 + col];
            g_cp[q][Ib][J0 + col] = s;
        }
        __syncthreads();
    }

    // ---- final row-partial write ----
    #pragma unroll
    for (int d = 1; d < 4; d <<= 1) {
        rs_aa0 += __shfl_down_sync(0xffffffffu, rs_aa0, d, 4);
        rs_aa1 += __shfl_down_sync(0xffffffffu, rs_aa1, d, 4);
        rm_aa0 += __shfl_down_sync(0xffffffffu, rm_aa0, d, 4);
        rm_aa1 += __shfl_down_sync(0xffffffffu, rm_aa1, d, 4);
        rs_ab0 += __shfl_down_sync(0xffffffffu, rs_ab0, d, 4);
        rs_ab1 += __shfl_down_sync(0xffffffffu, rs_ab1, d, 4);
        rm_ab0 += __shfl_down_sync(0xffffffffu, rm_ab0, d, 4);
        rm_ab1 += __shfl_down_sync(0xffffffffu, rm_ab1, d, 4);
    }
    if ((lane & 3) == 0) {
        int r0 = I + w * 16 + (lane >> 2);
        g_rp[c][0][r0]     = rs_aa0;
        g_rp[c][0][r0 + 8] = rs_aa1;
        g_rp[c][1][r0]     = rm_aa0;
        g_rp[c][1][r0 + 8] = rm_aa1;
        g_rp[c][2][r0]     = rs_ab0;
        g_rp[c][2][r0 + 8] = rs_ab1;
        g_rp[c][3][r0]     = rm_ab0;
        g_rp[c][3][r0 + 8] = rm_ab1;
    }
}

// ---------------- combine partials -> per-row losses ------------------------
__global__ __launch_bounds__(256) void rowloss2_kernel()
{
    int i = blockIdx.x * 256 + threadIdx.x;
    float aas = 0, aam = 0, abs_ = 0, abm = 0;
    #pragma unroll
    for (int c = 0; c < NCHUNK; c++) {
        aas  += g_rp[c][0][i];
        aam  += g_rp[c][1][i];
        abs_ += g_rp[c][2][i];
        abm  += g_rp[c][3][i];
    }
    float cabs = 0, cabm = 0, cbbs = 0, cbbm = 0;
    for (int b = 0; b < NIB; b++) {
        cabs += g_cp[0][b][i];
        cabm += g_cp[1][b][i];
        cbbs += g_cp[2][b][i];
        cbbm += g_cp[3][b][i];
    }
    g_rowloss[i]         = -logf(abm / (aas + abs_ - aam));
    g_rowloss[NROWS + i] = -logf(cabm / (cbbs + cabs - cbbm));
}

// ---------------- column means of z1, z2 (readout s) -----------------------
__global__ __launch_bounds__(512) void colmean_kernel(const float* __restrict__ z1,
                                                      const float* __restrict__ z2)
{
    const float* z = blockIdx.x ? z2 : z1;
    const int t = threadIdx.x;
    float a0 = 0, a1 = 0, a2 = 0, a3 = 0;
    for (int r = 0; r < NROWS; r += 4) {
        a0 += z[(size_t)(r+0) * DDIM + t];
        a1 += z[(size_t)(r+1) * DDIM + t];
        a2 += z[(size_t)(r+2) * DDIM + t];
        a3 += z[(size_t)(r+3) * DDIM + t];
    }
    g_s[blockIdx.x * DDIM + t] = (a0 + a1 + a2 + a3) * (1.0f / NROWS);
}

// ---------------- global projector chain: summ_p = W @ proj(s_p) -----------
__device__ __forceinline__ void mv_stage(const float* __restrict__ Wm,
                                         const float* __restrict__ bias,
                                         const float* vin, float* vout,
                                         float pa, bool prelu_on,
                                         int warp, int lane)
{
    for (int rr = 0; rr < 32; rr++) {
        int o = warp * 32 + rr;
        const float* wr = Wm + (size_t)o * DDIM;
        float acc = 0.0f;
        for (int i = lane; i < DDIM; i += 32) acc += wr[i] * vin[i];
        #pragma unroll
        for (int off = 16; off; off >>= 1) acc += __shfl_down_sync(0xffffffffu, acc, off);
        if (lane == 0) {
            float v = acc + (bias ? bias[o] : 0.0f);
            if (prelu_on) v = (v >= 0.0f) ? v : pa * v;
            vout[o] = v;
        }
    }
}

__global__ __launch_bounds__(512) void gproj_kernel(
    const float* __restrict__ gw1, const float* __restrict__ gb1,
    const float* __restrict__ ga,  const float* __restrict__ gw2,
    const float* __restrict__ gb2, const float* __restrict__ W)
{
    __shared__ float v[DDIM], u[DDIM], hh[DDIM];
    const int p = blockIdx.x;
    const int t = threadIdx.x, warp = t >> 5, lane = t & 31;
    v[t] = g_s[p * DDIM + t];
    __syncthreads();
    mv_stage(gw1, gb1, v, u, ga[0], true, warp, lane);
    __syncthreads();
    mv_stage(gw2, gb2, u, hh, 0.0f, false, warp, lane);
    __syncthreads();
    for (int rr = 0; rr < 32; rr++) {
        int o = warp * 32 + rr;
        const float* wr = W + (size_t)o * DDIM;
        float acc = 0.0f;
        for (int i = lane; i < DDIM; i += 32) acc += wr[i] * hh[i];
        #pragma unroll
        for (int off = 16; off; off >>= 1) acc += __shfl_down_sync(0xffffffffu, acc, off);
        if (lane == 0) g_summ[p * DDIM + o] = acc;
    }
}

// ---------------- per-row discriminator terms ------------------------------
__global__ __launch_bounds__(256) void sigrows_kernel(const float* __restrict__ z1,
                                                      const float* __restrict__ z2)
{
    const int warp = threadIdx.x >> 5, lane = threadIdx.x & 31;
    const int row = blockIdx.x * 8 + warp;
    const float* r1 = z1 + (size_t)row * DDIM;
    const float* r2 = z2 + (size_t)row * DDIM;
    float d11 = 0, d12 = 0, d21 = 0, d22 = 0;
    for (int i = lane; i < DDIM; i += 32) {
        float a = r1[i], b = r2[i];
        float s1 = g_summ[i], s2 = g_summ[DDIM + i];
        d11 += a * s1; d12 += a * s2; d21 += b * s1; d22 += b * s2;
    }
    #pragma unroll
    for (int off = 16; off; off >>= 1) {
        d11 += __shfl_down_sync(0xffffffffu, d11, off);
        d12 += __shfl_down_sync(0xffffffffu, d12, off);
        d21 += __shfl_down_sync(0xffffffffu, d21, off);
        d22 += __shfl_down_sync(0xffffffffu, d22, off);
    }
    if (lane == 0) {
        float sg11 = 1.0f / (1.0f + expf(-d11));
        float sg21 = 1.0f / (1.0f + expf(-d21));
        float sg22 = 1.0f / (1.0f + expf(-d22));
        float sg12 = 1.0f / (1.0f + expf(-d12));
        g_gl[0 * NROWS + row] = -logf(sg11 + EPS_);
        g_gl[1 * NROWS + row] = -logf(1.0f - sg21 + EPS_);
        g_gl[2 * NROWS + row] = -logf(sg22 + EPS_);
        g_gl[3 * NROWS + row] = -logf(1.0f - sg12 + EPS_);
    }
}

// ---------------- final deterministic reduction ----------------------------
__global__ __launch_bounds__(1024) void finalize_kernel(float* __restrict__ out)
{
    __shared__ float red[32];
    float acc[6] = {0, 0, 0, 0, 0, 0};
    for (int i = threadIdx.x; i < NROWS; i += 1024) {
        acc[0] += g_rowloss[i];
        acc[1] += g_rowloss[NROWS + i];
        acc[2] += g_gl[i];
        acc[3] += g_gl[NROWS + i];
        acc[4] += g_gl[2 * NROWS + i];
        acc[5] += g_gl[3 * NROWS + i];
    }
    const int lane = threadIdx.x & 31, warp = threadIdx.x >> 5;
    float tot[6];
    for (int q = 0; q < 6; q++) {
        float v = acc[q];
        #pragma unroll
        for (int off = 16; off; off >>= 1) v += __shfl_down_sync(0xffffffffu, v, off);
        if (lane == 0) red[warp] = v;
        __syncthreads();
        if (warp == 0) {
            float w = red[lane];
            #pragma unroll
            for (int off = 16; off; off >>= 1) w += __shfl_down_sync(0xffffffffu, w, off);
            if (lane == 0) tot[q] = w;
        }
        __syncthreads();
    }
    if (threadIdx.x == 0) {
        const float inv = 1.0f / NROWS;
        float local = 0.5f * (tot[0] + tot[1]) * inv;
        float gl1   = 0.5f * (tot[2] + tot[3]) * inv;
        float gl2   = 0.5f * (tot[4] + tot[5]) * inv;
        float glob  = 0.5f * (gl1 + gl2);
        out[0] = 0.5f * local + 0.5f * glob;   // ALPHA = 0.5
    }
}

// ---------------- launch ----------------------------------------------------
extern "C" void kernel_launch(void* const* d_in, const int* in_sizes, int n_in,
                              void* d_out, int out_size)
{
    const float* z1  = (const float*)d_in[0];
    const float* z2  = (const float*)d_in[1];
    const float* lw1 = (const float*)d_in[2];
    const float* lb1 = (const float*)d_in[3];
    const float* la  = (const float*)d_in[4];
    const float* lw2 = (const float*)d_in[5];
    const float* lb2 = (const float*)d_in[6];
    const float* gw1 = (const float*)d_in[7];
    const float* gb1 = (const float*)d_in[8];
    const float* ga  = (const float*)d_in[9];
    const float* gw2 = (const float*)d_in[10];
    const float* gb2 = (const float*)d_in[11];
    const float* W   = (const float*)d_in[12];
    const int*   mask= (const int*)  d_in[13];
    float* out = (float*)d_out;

    cudaFuncSetAttribute(sim_kernel, cudaFuncAttributeMaxDynamicSharedMemorySize,
                         SIM_SMEM_BYTES);

    // bf16 conversions
    conv_bf16_kernel<<<2048, 256>>>(z1,  0, NROWS * DDIM / 4);
    conv_bf16_kernel<<<2048, 256>>>(z2,  1, NROWS * DDIM / 4);
    conv_bf16_kernel<<<256,  256>>>(lw1, 2, DDIM * DDIM / 4);
    conv_bf16_kernel<<<256,  256>>>(lw2, 3, DDIM * DDIM / 4);

    // projector: stage 1 (both views), stage 2 (both views)
    gemm_hmma_kernel<<<dim3(32, 4, 2), 256>>>(lb1, la, 1);
    gemm_hmma_kernel<<<dim3(32, 4, 2), 256>>>(lb2, nullptr, 2);

    l2norm_kernel<<<dim3(NROWS, 2), 128>>>();

    sim_kernel<<<dim3(NIB, NCHUNK), 256, SIM_SMEM_BYTES>>>(mask);
    rowloss2_kernel<<<NROWS / 256, 256>>>();

    colmean_kernel<<<2, DDIM>>>(z1, z2);
    gproj_kernel<<<2, DDIM>>>(gw1, gb1, ga, gw2, gb2, W);
    sigrows_kernel<<<NROWS / 8, 256>>>(z1, z2);

    finalize_kernel<<<1, 1024>>>(out);
}

// round 7
// speedup vs baseline: 5.0532x; 1.0361x over previous
#include <cuda_runtime.h>
#include <cuda_bf16.h>
#include <math.h>
#include <cstdint>

#define NROWS 4096
#define DDIM  512
#define INV_TAU 5.0f
#define EPS_  1e-15f
#define L2EPS 1e-12f

#define NCHUNK 4
#define CHUNKJ (NROWS / NCHUNK)   // 1024
#define IT 128
#define NIB (NROWS / IT)          // 32

// sim kernel: 3-stage ring of 64-wide k-slabs, padded row stride 72 bf16 (144B)
#define S_AI 0
#define S_BI 18432
#define S_AJ 36864
#define S_BJ 46080
#define SIM_STAGE 55296
#define SIM_SMEM_BYTES (3 * SIM_STAGE + 8192)

// gemm kernel: 3-stage ring of 32-wide k-slabs, row stride 40 bf16 (80B)
#define G_STAGE 20480
#define GEMM_SMEM_BYTES (3 * G_STAGE)

typedef unsigned long long u64;

// ---------------- scratch (static device allocations; no cudaMalloc) ------
__device__ __nv_bfloat16 g_z16a[NROWS * DDIM];
__device__ __nv_bfloat16 g_z16b[NROWS * DDIM];
__device__ __nv_bfloat16 g_T16a[NROWS * DDIM];
__device__ __nv_bfloat16 g_T16b[NROWS * DDIM];
__device__ __nv_bfloat16 g_H16a[NROWS * DDIM];
__device__ __nv_bfloat16 g_H16b[NROWS * DDIM];
__device__ __nv_bfloat16 g_w1s[DDIM * DDIM];
__device__ __nv_bfloat16 g_w2s[DDIM * DDIM];
__device__ __nv_bfloat16 g_a16[NROWS * DDIM];
__device__ __nv_bfloat16 g_b16[NROWS * DDIM];
__device__ float g_rowloss[2 * NROWS];
__device__ float g_gl[4 * NROWS];
__device__ float g_s[2 * DDIM];
__device__ float g_summ[2 * DDIM];
__device__ float g_rp[NCHUNK][4][NROWS];  // row partials: aaS,aaM,abS,abM
__device__ float g_cp[4][NIB][NROWS];     // col partials: abS,abM,bbS,bbM

// ---------------- PTX helpers ----------------------------------------------
__device__ __forceinline__ uint32_t smem_u32(const void* p) {
    uint32_t a;
    asm("{ .reg .u64 tmp; cvta.to.shared.u64 tmp, %1; cvt.u32.u64 %0, tmp; }"
        : "=r"(a) : "l"(p));
    return a;
}

__device__ __forceinline__ void ldm4(uint32_t* r, uint32_t addr) {
    asm volatile("ldmatrix.sync.aligned.m8n8.x4.shared.b16 {%0,%1,%2,%3}, [%4];"
                 : "=r"(r[0]), "=r"(r[1]), "=r"(r[2]), "=r"(r[3]) : "r"(addr));
}

__device__ __forceinline__ void mma16816(float* c, const uint32_t* a,
                                         uint32_t b0, uint32_t b1) {
    asm volatile("mma.sync.aligned.m16n8k16.row.col.f32.bf16.bf16.f32 "
                 "{%0,%1,%2,%3}, {%4,%5,%6,%7}, {%8,%9}, {%0,%1,%2,%3};"
                 : "+f"(c[0]), "+f"(c[1]), "+f"(c[2]), "+f"(c[3])
                 : "r"(a[0]), "r"(a[1]), "r"(a[2]), "r"(a[3]), "r"(b0), "r"(b1));
}

__device__ __forceinline__ void cpa16(uint32_t dst, const void* src) {
    asm volatile("cp.async.cg.shared.global [%0], [%1], 16;"
                 :: "r"(dst), "l"(src) : "memory");
}
#define CP_COMMIT() asm volatile("cp.async.commit_group;" ::: "memory")
template <int N>
__device__ __forceinline__ void cp_wait() {
    asm volatile("cp.async.wait_group %0;" :: "n"(N) : "memory");
}

// ---------------- fp32 -> bf16 conversion -----------------------------------
__global__ __launch_bounds__(256) void conv_bf16_kernel(const float* __restrict__ src,
                                                        int dst_sel, int n4)
{
    int i = blockIdx.x * 256 + threadIdx.x;
    if (i >= n4) return;
    __nv_bfloat16* dst = dst_sel == 0 ? g_z16a : dst_sel == 1 ? g_z16b
                       : dst_sel == 2 ? g_w1s  : g_w2s;
    float4 v = ((const float4*)src)[i];
    __nv_bfloat162* d = (__nv_bfloat162*)(dst + (size_t)i * 4);
    d[0] = __float22bfloat162_rn(make_float2(v.x, v.y));
    d[1] = __float22bfloat162_rn(make_float2(v.z, v.w));
}

// ---------------- HMMA projector GEMM (3-stage ring) ------------------------
// C[4096,512] = A @ W^T + bias (optional PReLU), bf16 out.
// stage 1: A=g_z16{a,b}, W=g_w1s, out=g_T16{a,b}
// stage 2: A=g_T16{a,b}, W=g_w2s, out=g_H16{a,b}
__global__ __launch_bounds__(256, 1) void gemm_hmma_kernel(
    const float* __restrict__ bias, const float* __restrict__ prelu_a, int stage)
{
    extern __shared__ __align__(16) char gsm[];
    const uint32_t u0 = smem_u32(gsm);

    const int t = threadIdx.x, w = t >> 5, lane = t & 31;
    const int I0 = blockIdx.x * 128, J0 = blockIdx.y * 128;
    const int z = blockIdx.z;

    const __nv_bfloat16* __restrict__ A =
        (stage == 1) ? (z ? g_z16b : g_z16a) : (z ? g_T16b : g_T16a);
    const __nv_bfloat16* __restrict__ Wm = (stage == 1) ? g_w1s : g_w2s;

    const int lr16 = lane & 15, lh = lane >> 4;
    const uint32_t aoff = (w * 16 + lr16) * 80 + lh * 16;
    uint32_t boff[8];
    #pragma unroll
    for (int p = 0; p < 8; p++)
        boff[p] = (p * 16 + lr16) * 80 + lh * 16;

    // cp.async mapping: 512 16B-chunks per array, 2 per thread
    int rr[2], cc8[2];
    uint32_t dd[2];
    #pragma unroll
    for (int q = 0; q < 2; q++) {
        int id = t + q * 256;
        rr[q] = id >> 2; cc8[q] = (id & 3) * 8;
        dd[q] = rr[q] * 80 + (id & 3) * 16;
    }

    float acc[8][2][4];
    #pragma unroll
    for (int p = 0; p < 8; p++)
        #pragma unroll
        for (int h = 0; h < 2; h++)
            #pragma unroll
            for (int q = 0; q < 4; q++) acc[p][h][q] = 0.0f;

    // prologue: stages 0, 1
    #pragma unroll
    for (int s = 0; s < 2; s++) {
        const uint32_t b = u0 + s * G_STAGE;
        const int kb = s * 32;
        #pragma unroll
        for (int q = 0; q < 2; q++) {
            cpa16(b + dd[q], A + (size_t)(I0 + rr[q]) * DDIM + kb + cc8[q]);
            cpa16(b + 10240 + dd[q], Wm + (size_t)(J0 + rr[q]) * DDIM + kb + cc8[q]);
        }
        CP_COMMIT();
    }

    for (int ck = 0; ck < 16; ck++) {
        cp_wait<1>();
        __syncthreads();
        if (ck + 2 < 16) {
            const uint32_t b = u0 + ((ck + 2) % 3) * G_STAGE;
            const int kb = (ck + 2) * 32;
            #pragma unroll
            for (int q = 0; q < 2; q++) {
                cpa16(b + dd[q], A + (size_t)(I0 + rr[q]) * DDIM + kb + cc8[q]);
                cpa16(b + 10240 + dd[q], Wm + (size_t)(J0 + rr[q]) * DDIM + kb + cc8[q]);
            }
        }
        CP_COMMIT();
        const uint32_t uA = u0 + (ck % 3) * G_STAGE;
        const uint32_t uW = uA + 10240;
        #pragma unroll
        for (int ks = 0; ks < 2; ks++) {
            uint32_t fA[4];
            ldm4(fA, uA + aoff + ks * 32);
            #pragma unroll
            for (int p = 0; p < 8; p++) {
                uint32_t fW[4];
                ldm4(fW, uW + boff[p] + ks * 32);
                mma16816(acc[p][0], fA, fW[0], fW[2]);
                mma16816(acc[p][1], fA, fW[1], fW[3]);
            }
        }
    }

    // epilogue (bf16 out)
    const int er = lane >> 2, ec = 2 * (lane & 3);
    const int row = I0 + w * 16 + er;
    const bool do_prelu = (prelu_a != nullptr);
    const float pa = do_prelu ? prelu_a[0] : 0.0f;

    __nv_bfloat16* Out = (stage == 1) ? (z ? g_T16b : g_T16a)
                                      : (z ? g_H16b : g_H16a);
    #pragma unroll
    for (int p = 0; p < 8; p++) {
        #pragma unroll
        for (int h = 0; h < 2; h++) {
            int col = J0 + p * 16 + h * 8 + ec;
            float b0 = bias[col], b1 = bias[col + 1];
            float v0 = acc[p][h][0] + b0, v1 = acc[p][h][1] + b1;
            float v2 = acc[p][h][2] + b0, v3 = acc[p][h][3] + b1;
            if (do_prelu) {
                v0 = (v0 >= 0.0f) ? v0 : pa * v0;
                v1 = (v1 >= 0.0f) ? v1 : pa * v1;
                v2 = (v2 >= 0.0f) ? v2 : pa * v2;
                v3 = (v3 >= 0.0f) ? v3 : pa * v3;
            }
            *(__nv_bfloat162*)(Out + (size_t)row * DDIM + col) =
                __float22bfloat162_rn(make_float2(v0, v1));
            *(__nv_bfloat162*)(Out + (size_t)(row + 8) * DDIM + col) =
                __float22bfloat162_rn(make_float2(v2, v3));
        }
    }
}

// ---------------- row L2 normalization (bf16 in -> bf16 out) ----------------
__global__ __launch_bounds__(128) void l2norm_kernel()
{
    const __nv_bfloat16* h = blockIdx.y ? g_H16b : g_H16a;
    __nv_bfloat16* o16 = blockIdx.y ? g_b16 : g_a16;
    const int row = blockIdx.x;
    const int t = threadIdx.x;
    const __nv_bfloat162* src = (const __nv_bfloat162*)&h[(size_t)row * DDIM + t*4];
    __nv_bfloat162 h0 = src[0], h1 = src[1];
    float2 f0 = __bfloat1622float2(h0), f1 = __bfloat1622float2(h1);
    float ss = f0.x*f0.x + f0.y*f0.y + f1.x*f1.x + f1.y*f1.y;
    #pragma unroll
    for (int off = 16; off; off >>= 1) ss += __shfl_down_sync(0xffffffffu, ss, off);
    __shared__ float sm[4];
    __shared__ float stot;
    if ((t & 31) == 0) sm[t >> 5] = ss;
    __syncthreads();
    if (t == 0) stot = sm[0] + sm[1] + sm[2] + sm[3];
    __syncthreads();
    float scale = 1.0f / fmaxf(sqrtf(stot), L2EPS);
    __nv_bfloat162* dst = (__nv_bfloat162*)&o16[(size_t)row * DDIM + t*4];
    dst[0] = __float22bfloat162_rn(make_float2(f0.x * scale, f0.y * scale));
    dst[1] = __float22bfloat162_rn(make_float2(f1.x * scale, f1.y * scale));
}

// ---------------- HMMA similarity kernel (3-stage ring, 64-k slabs) ---------
// CTA (Ib, c): I-rows Ib*128..+127; 16 J-tiles of 64 in chunk c.
// aa = a_I.a_J^T, ab = a_I.b_J^T, bb = b_I.b_J^T.
// Row sums (aa, ab) -> g_rp[c]; col sums (ab, bb) -> g_cp[.][Ib].
__global__ __launch_bounds__(256, 1) void sim_kernel(const int* __restrict__ mask)
{
    extern __shared__ __align__(16) char dsm[];
    const uint32_t u0 = smem_u32(dsm);
    float* sred = (float*)(dsm + 3 * SIM_STAGE);

    const int t = threadIdx.x, w = t >> 5, lane = t & 31;
    const int Ib = blockIdx.x, c = blockIdx.y;
    const int I = Ib * IT;
    const int Jbase = c * CHUNKJ;

    const int lr16 = lane & 15, lh = lane >> 4;
    const uint32_t aoff = (w * 16 + lr16) * 144 + lh * 16;
    uint32_t boff[4];
    #pragma unroll
    for (int p = 0; p < 4; p++)
        boff[p] = (p * 16 + lr16) * 144 + lh * 16;

    // cp.async mapping (row stride 144B)
    int rI[4], cI8[4];
    uint32_t dI[4];
    #pragma unroll
    for (int q = 0; q < 4; q++) {
        int id = t + q * 256;
        rI[q] = id >> 3; cI8[q] = (id & 7) * 8;
        dI[q] = rI[q] * 144 + (id & 7) * 16;
    }

    const int er = lane >> 2;
    const int ec = 2 * (lane & 3);
    const size_t gr0 = (size_t)(I + w * 16 + er);

    float rs_aa0 = 0, rs_aa1 = 0, rm_aa0 = 0, rm_aa1 = 0;
    float rs_ab0 = 0, rs_ab1 = 0, rm_ab0 = 0, rm_ab1 = 0;

    float acc[3][8][4];
    #pragma unroll
    for (int m = 0; m < 3; m++)
        #pragma unroll
        for (int nb = 0; nb < 8; nb++)
            #pragma unroll
            for (int q = 0; q < 4; q++) acc[m][nb][q] = 0.0f;

    // stage issue lambda-equivalent
    #define SIM_ISSUE(sidx)                                                     \
    do {                                                                        \
        const int _s = (sidx);                                                  \
        const uint32_t _b = u0 + (_s % 3) * SIM_STAGE;                          \
        const int _J0 = Jbase + (_s >> 3) * 64;                                 \
        const int _kb = (_s & 7) * 64;                                          \
        _Pragma("unroll")                                                       \
        for (int q = 0; q < 4; q++) {                                           \
            cpa16(_b + S_AI + dI[q], g_a16 + (size_t)(I + rI[q]) * DDIM + _kb + cI8[q]); \
            cpa16(_b + S_BI + dI[q], g_b16 + (size_t)(I + rI[q]) * DDIM + _kb + cI8[q]); \
        }                                                                       \
        _Pragma("unroll")                                                       \
        for (int q = 0; q < 2; q++) {                                           \
            cpa16(_b + S_AJ + dI[q], g_a16 + (size_t)(_J0 + rI[q]) * DDIM + _kb + cI8[q]); \
            cpa16(_b + S_BJ + dI[q], g_b16 + (size_t)(_J0 + rI[q]) * DDIM + _kb + cI8[q]); \
        }                                                                       \
    } while (0)

    SIM_ISSUE(0); CP_COMMIT();
    SIM_ISSUE(1); CP_COMMIT();

    for (int s = 0; s < 128; s++) {
        cp_wait<1>();
        __syncthreads();
        if (s + 2 < 128) SIM_ISSUE(s + 2);
        CP_COMMIT();

        const uint32_t bc = u0 + (s % 3) * SIM_STAGE;
        const uint32_t uAI = bc + S_AI, uBI = bc + S_BI;
        const uint32_t uAJ = bc + S_AJ, uBJ = bc + S_BJ;
        #pragma unroll
        for (int ks = 0; ks < 4; ks++) {
            uint32_t fA[4], fB[4], fAJ[4][4], fBJ[4][4];
            ldm4(fA, uAI + aoff + ks * 32);
            ldm4(fB, uBI + aoff + ks * 32);
            #pragma unroll
            for (int p = 0; p < 4; p++) {
                ldm4(fAJ[p], uAJ + boff[p] + ks * 32);
                ldm4(fBJ[p], uBJ + boff[p] + ks * 32);
            }
            #pragma unroll
            for (int p = 0; p < 4; p++) {
                mma16816(acc[0][2*p],   fA, fAJ[p][0], fAJ[p][2]);
                mma16816(acc[0][2*p+1], fA, fAJ[p][1], fAJ[p][3]);
                mma16816(acc[1][2*p],   fA, fBJ[p][0], fBJ[p][2]);
                mma16816(acc[1][2*p+1], fA, fBJ[p][1], fBJ[p][3]);
                mma16816(acc[2][2*p],   fB, fBJ[p][0], fBJ[p][2]);
                mma16816(acc[2][2*p+1], fB, fBJ[p][1], fBJ[p][3]);
            }
        }

        if ((s & 7) == 7) {
            // ---- epilogue for tile jt = s>>3 ----
            const int J0 = Jbase + (s >> 3) * 64;
            #pragma unroll
            for (int nb = 0; nb < 8; nb++) {
                const int gc = J0 + nb * 8 + ec;
                int2 m0 = *(const int2*)(mask + gr0 * NROWS + gc);
                int2 m1 = *(const int2*)(mask + (gr0 + 8) * NROWS + gc);
                float m00 = (float)m0.x, m01 = (float)m0.y;
                float m10 = (float)m1.x, m11 = (float)m1.y;

                float ea0 = __expf(acc[0][nb][0] * INV_TAU);
                float ea1 = __expf(acc[0][nb][1] * INV_TAU);
                float ea2 = __expf(acc[0][nb][2] * INV_TAU);
                float ea3 = __expf(acc[0][nb][3] * INV_TAU);
                float eb0 = __expf(acc[1][nb][0] * INV_TAU);
                float eb1 = __expf(acc[1][nb][1] * INV_TAU);
                float eb2 = __expf(acc[1][nb][2] * INV_TAU);
                float eb3 = __expf(acc[1][nb][3] * INV_TAU);
                float ec0 = __expf(acc[2][nb][0] * INV_TAU);
                float ec1 = __expf(acc[2][nb][1] * INV_TAU);
                float ec2 = __expf(acc[2][nb][2] * INV_TAU);
                float ec3 = __expf(acc[2][nb][3] * INV_TAU);

                rs_aa0 += ea0 + ea1;  rm_aa0 += ea0 * m00 + ea1 * m01;
                rs_aa1 += ea2 + ea3;  rm_aa1 += ea2 * m10 + ea3 * m11;
                rs_ab0 += eb0 + eb1;  rm_ab0 += eb0 * m00 + eb1 * m01;
                rs_ab1 += eb2 + eb3;  rm_ab1 += eb2 * m10 + eb3 * m11;

                float v[8];
                v[0] = eb0 + eb2;              v[1] = eb1 + eb3;
                v[2] = eb0 * m00 + eb2 * m10;  v[3] = eb1 * m01 + eb3 * m11;
                v[4] = ec0 + ec2;              v[5] = ec1 + ec3;
                v[6] = ec0 * m00 + ec2 * m10;  v[7] = ec1 * m01 + ec3 * m11;
                #pragma unroll
                for (int q = 0; q < 8; q++) {
                    v[q] += __shfl_down_sync(0xffffffffu, v[q], 16);
                    v[q] += __shfl_down_sync(0xffffffffu, v[q], 8);
                    v[q] += __shfl_down_sync(0xffffffffu, v[q], 4);
                }
                if (lane < 4) {
                    int col = nb * 8 + 2 * lane;
                    sred[(w * 4 + 0) * 64 + col]     = v[0];
                    sred[(w * 4 + 0) * 64 + col + 1] = v[1];
                    sred[(w * 4 + 1) * 64 + col]     = v[2];
                    sred[(w * 4 + 1) * 64 + col + 1] = v[3];
                    sred[(w * 4 + 2) * 64 + col]     = v[4];
                    sred[(w * 4 + 2) * 64 + col + 1] = v[5];
                    sred[(w * 4 + 3) * 64 + col]     = v[6];
                    sred[(w * 4 + 3) * 64 + col + 1] = v[7];
                }
            }
            __syncthreads();
            {
                int q = t >> 6, col = t & 63;
                float sacc = 0.0f;
                #pragma unroll
                for (int ww = 0; ww < 8; ww++)
                    sacc += sred[(ww * 4 + q) * 64 + col];
                g_cp[q][Ib][J0 + col] = sacc;
            }
            #pragma unroll
            for (int m = 0; m < 3; m++)
                #pragma unroll
                for (int nb = 0; nb < 8; nb++)
                    #pragma unroll
                    for (int q = 0; q < 4; q++) acc[m][nb][q] = 0.0f;
        }
    }

    // ---- final row-partial write ----
    #pragma unroll
    for (int d = 1; d < 4; d <<= 1) {
        rs_aa0 += __shfl_down_sync(0xffffffffu, rs_aa0, d, 4);
        rs_aa1 += __shfl_down_sync(0xffffffffu, rs_aa1, d, 4);
        rm_aa0 += __shfl_down_sync(0xffffffffu, rm_aa0, d, 4);
        rm_aa1 += __shfl_down_sync(0xffffffffu, rm_aa1, d, 4);
        rs_ab0 += __shfl_down_sync(0xffffffffu, rs_ab0, d, 4);
        rs_ab1 += __shfl_down_sync(0xffffffffu, rs_ab1, d, 4);
        rm_ab0 += __shfl_down_sync(0xffffffffu, rm_ab0, d, 4);
        rm_ab1 += __shfl_down_sync(0xffffffffu, rm_ab1, d, 4);
    }
    if ((lane & 3) == 0) {
        int r0 = I + w * 16 + (lane >> 2);
        g_rp[c][0][r0]     = rs_aa0;
        g_rp[c][0][r0 + 8] = rs_aa1;
        g_rp[c][1][r0]     = rm_aa0;
        g_rp[c][1][r0 + 8] = rm_aa1;
        g_rp[c][2][r0]     = rs_ab0;
        g_rp[c][2][r0 + 8] = rs_ab1;
        g_rp[c][3][r0]     = rm_ab0;
        g_rp[c][3][r0 + 8] = rm_ab1;
    }
}

// ---------------- combine partials -> per-row losses ------------------------
__global__ __launch_bounds__(256) void rowloss2_kernel()
{
    int i = blockIdx.x * 256 + threadIdx.x;
    float aas = 0, aam = 0, abs_ = 0, abm = 0;
    #pragma unroll
    for (int c = 0; c < NCHUNK; c++) {
        aas  += g_rp[c][0][i];
        aam  += g_rp[c][1][i];
        abs_ += g_rp[c][2][i];
        abm  += g_rp[c][3][i];
    }
    float cabs = 0, cabm = 0, cbbs = 0, cbbm = 0;
    for (int b = 0; b < NIB; b++) {
        cabs += g_cp[0][b][i];
        cabm += g_cp[1][b][i];
        cbbs += g_cp[2][b][i];
        cbbm += g_cp[3][b][i];
    }
    g_rowloss[i]         = -logf(abm / (aas + abs_ - aam));
    g_rowloss[NROWS + i] = -logf(cabm / (cbbs + cabs - cbbm));
}

// ---------------- column means of z1, z2 (readout s) -----------------------
__global__ __launch_bounds__(512) void colmean_kernel(const float* __restrict__ z1,
                                                      const float* __restrict__ z2)
{
    const float* z = blockIdx.x ? z2 : z1;
    const int t = threadIdx.x;
    float a0 = 0, a1 = 0, a2 = 0, a3 = 0;
    for (int r = 0; r < NROWS; r += 4) {
        a0 += z[(size_t)(r+0) * DDIM + t];
        a1 += z[(size_t)(r+1) * DDIM + t];
        a2 += z[(size_t)(r+2) * DDIM + t];
        a3 += z[(size_t)(r+3) * DDIM + t];
    }
    g_s[blockIdx.x * DDIM + t] = (a0 + a1 + a2 + a3) * (1.0f / NROWS);
}

// ---------------- global projector chain: summ_p = W @ proj(s_p) -----------
__device__ __forceinline__ void mv_stage(const float* __restrict__ Wm,
                                         const float* __restrict__ bias,
                                         const float* vin, float* vout,
                                         float pa, bool prelu_on,
                                         int warp, int lane)
{
    for (int rr = 0; rr < 32; rr++) {
        int o = warp * 32 + rr;
        const float* wr = Wm + (size_t)o * DDIM;
        float acc = 0.0f;
        for (int i = lane; i < DDIM; i += 32) acc += wr[i] * vin[i];
        #pragma unroll
        for (int off = 16; off; off >>= 1) acc += __shfl_down_sync(0xffffffffu, acc, off);
        if (lane == 0) {
            float v = acc + (bias ? bias[o] : 0.0f);
            if (prelu_on) v = (v >= 0.0f) ? v : pa * v;
            vout[o] = v;
        }
    }
}

__global__ __launch_bounds__(512) void gproj_kernel(
    const float* __restrict__ gw1, const float* __restrict__ gb1,
    const float* __restrict__ ga,  const float* __restrict__ gw2,
    const float* __restrict__ gb2, const float* __restrict__ W)
{
    __shared__ float v[DDIM], u[DDIM], hh[DDIM];
    const int p = blockIdx.x;
    const int t = threadIdx.x, warp = t >> 5, lane = t & 31;
    v[t] = g_s[p * DDIM + t];
    __syncthreads();
    mv_stage(gw1, gb1, v, u, ga[0], true, warp, lane);
    __syncthreads();
    mv_stage(gw2, gb2, u, hh, 0.0f, false, warp, lane);
    __syncthreads();
    for (int rr = 0; rr < 32; rr++) {
        int o = warp * 32 + rr;
        const float* wr = W + (size_t)o * DDIM;
        float acc = 0.0f;
        for (int i = lane; i < DDIM; i += 32) acc += wr[i] * hh[i];
        #pragma unroll
        for (int off = 16; off; off >>= 1) acc += __shfl_down_sync(0xffffffffu, acc, off);
        if (lane == 0) g_summ[p * DDIM + o] = acc;
    }
}

// ---------------- per-row discriminator terms ------------------------------
__global__ __launch_bounds__(256) void sigrows_kernel(const float* __restrict__ z1,
                                                      const float* __restrict__ z2)
{
    const int warp = threadIdx.x >> 5, lane = threadIdx.x & 31;
    const int row = blockIdx.x * 8 + warp;
    const float* r1 = z1 + (size_t)row * DDIM;
    const float* r2 = z2 + (size_t)row * DDIM;
    float d11 = 0, d12 = 0, d21 = 0, d22 = 0;
    for (int i = lane; i < DDIM; i += 32) {
        float a = r1[i], b = r2[i];
        float s1 = g_summ[i], s2 = g_summ[DDIM + i];
        d11 += a * s1; d12 += a * s2; d21 += b * s1; d22 += b * s2;
    }
    #pragma unroll
    for (int off = 16; off; off >>= 1) {
        d11 += __shfl_down_sync(0xffffffffu, d11, off);
        d12 += __shfl_down_sync(0xffffffffu, d12, off);
        d21 += __shfl_down_sync(0xffffffffu, d21, off);
        d22 += __shfl_down_sync(0xffffffffu, d22, off);
    }
    if (lane == 0) {
        float sg11 = 1.0f / (1.0f + expf(-d11));
        float sg21 = 1.0f / (1.0f + expf(-d21));
        float sg22 = 1.0f / (1.0f + expf(-d22));
        float sg12 = 1.0f / (1.0f + expf(-d12));
        g_gl[0 * NROWS + row] = -logf(sg11 + EPS_);
        g_gl[1 * NROWS + row] = -logf(1.0f - sg21 + EPS_);
        g_gl[2 * NROWS + row] = -logf(sg22 + EPS_);
        g_gl[3 * NROWS + row] = -logf(1.0f - sg12 + EPS_);
    }
}

// ---------------- final deterministic reduction ----------------------------
__global__ __launch_bounds__(1024) void finalize_kernel(float* __restrict__ out)
{
    __shared__ float red[32];
    float acc[6] = {0, 0, 0, 0, 0, 0};
    for (int i = threadIdx.x; i < NROWS; i += 1024) {
        acc[0] += g_rowloss[i];
        acc[1] += g_rowloss[NROWS + i];
        acc[2] += g_gl[i];
        acc[3] += g_gl[NROWS + i];
        acc[4] += g_gl[2 * NROWS + i];
        acc[5] += g_gl[3 * NROWS + i];
    }
    const int lane = threadIdx.x & 31, warp = threadIdx.x >> 5;
    float tot[6];
    for (int q = 0; q < 6; q++) {
        float v = acc[q];
        #pragma unroll
        for (int off = 16; off; off >>= 1) v += __shfl_down_sync(0xffffffffu, v, off);
        if (lane == 0) red[warp] = v;
        __syncthreads();
        if (warp == 0) {
            float w = red[lane];
            #pragma unroll
            for (int off = 16; off; off >>= 1) w += __shfl_down_sync(0xffffffffu, w, off);
            if (lane == 0) tot[q] = w;
        }
        __syncthreads();
    }
    if (threadIdx.x == 0) {
        const float inv = 1.0f / NROWS;
        float local = 0.5f * (tot[0] + tot[1]) * inv;
        float gl1   = 0.5f * (tot[2] + tot[3]) * inv;
        float gl2   = 0.5f * (tot[4] + tot[5]) * inv;
        float glob  = 0.5f * (gl1 + gl2);
        out[0] = 0.5f * local + 0.5f * glob;   // ALPHA = 0.5
    }
}

// ---------------- launch ----------------------------------------------------
extern "C" void kernel_launch(void* const* d_in, const int* in_sizes, int n_in,
                              void* d_out, int out_size)
{
    const float* z1  = (const float*)d_in[0];
    const float* z2  = (const float*)d_in[1];
    const float* lw1 = (const float*)d_in[2];
    const float* lb1 = (const float*)d_in[3];
    const float* la  = (const float*)d_in[4];
    const float* lw2 = (const float*)d_in[5];
    const float* lb2 = (const float*)d_in[6];
    const float* gw1 = (const float*)d_in[7];
    const float* gb1 = (const float*)d_in[8];
    const float* ga  = (const float*)d_in[9];
    const float* gw2 = (const float*)d_in[10];
    const float* gb2 = (const float*)d_in[11];
    const float* W   = (const float*)d_in[12];
    const int*   mask= (const int*)  d_in[13];
    float* out = (float*)d_out;

    cudaFuncSetAttribute(sim_kernel, cudaFuncAttributeMaxDynamicSharedMemorySize,
                         SIM_SMEM_BYTES);
    cudaFuncSetAttribute(gemm_hmma_kernel, cudaFuncAttributeMaxDynamicSharedMemorySize,
                         GEMM_SMEM_BYTES);

    // bf16 conversions
    conv_bf16_kernel<<<2048, 256>>>(z1,  0, NROWS * DDIM / 4);
    conv_bf16_kernel<<<2048, 256>>>(z2,  1, NROWS * DDIM / 4);
    conv_bf16_kernel<<<256,  256>>>(lw1, 2, DDIM * DDIM / 4);
    conv_bf16_kernel<<<256,  256>>>(lw2, 3, DDIM * DDIM / 4);

    // projector: stage 1 (both views), stage 2 (both views)
    gemm_hmma_kernel<<<dim3(32, 4, 2), 256, GEMM_SMEM_BYTES>>>(lb1, la, 1);
    gemm_hmma_kernel<<<dim3(32, 4, 2), 256, GEMM_SMEM_BYTES>>>(lb2, nullptr, 2);

    l2norm_kernel<<<dim3(NROWS, 2), 128>>>();

    sim_kernel<<<dim3(NIB, NCHUNK), 256, SIM_SMEM_BYTES>>>(mask);
    rowloss2_kernel<<<NROWS / 256, 256>>>();

    colmean_kernel<<<2, DDIM>>>(z1, z2);
    gproj_kernel<<<2, DDIM>>>(gw1, gb1, ga, gw2, gb2, W);
    sigrows_kernel<<<NROWS / 8, 256>>>(z1, z2);

    finalize_kernel<<<1, 1024>>>(out);
}

// round 8
// speedup vs baseline: 5.0764x; 1.0046x over previous
#include <cuda_runtime.h>
#include <cuda_bf16.h>
#include <cuda_fp8.h>
#include <math.h>
#include <cstdint>

#define NROWS 4096
#define DDIM  512
#define INV_TAU 5.0f
#define EXP_SCALE (INV_TAU / 256.0f)   // fp8 values scaled x16 -> dot x256
#define QSCL 16.0f
#define EPS_  1e-15f
#define L2EPS 1e-12f

#define NCHUNK 4
#define CHUNKJ (NROWS / NCHUNK)   // 1024
#define IT 128
#define NIB (NROWS / IT)          // 32

// sim kernel: 3-stage ring of 128-wide fp8 k-slabs, row stride 144B
#define S_AI 0
#define S_BI 18432
#define S_AJ 36864
#define S_BJ 46080
#define SIM_STAGE 55296
#define SIM_SMEM_BYTES (3 * SIM_STAGE + 8192)
#define NSTAGE 64          // 16 J-tiles x 4 slabs

// gemm kernel: 3-stage ring of 32-wide bf16 k-slabs, row stride 80B
#define G_STAGE 20480
#define GEMM_SMEM_BYTES (3 * G_STAGE)

typedef unsigned long long u64;

// ---------------- scratch (static device allocations; no cudaMalloc) ------
__device__ __nv_bfloat16 g_z16a[NROWS * DDIM];
__device__ __nv_bfloat16 g_z16b[NROWS * DDIM];
__device__ __nv_bfloat16 g_T16a[NROWS * DDIM];
__device__ __nv_bfloat16 g_T16b[NROWS * DDIM];
__device__ __nv_bfloat16 g_H16a[NROWS * DDIM];
__device__ __nv_bfloat16 g_H16b[NROWS * DDIM];
__device__ __nv_bfloat16 g_w1s[DDIM * DDIM];
__device__ __nv_bfloat16 g_w2s[DDIM * DDIM];
__device__ uint8_t g_a8[NROWS * DDIM];   // fp8 e4m3, scaled x16
__device__ uint8_t g_b8[NROWS * DDIM];
__device__ float g_rowloss[2 * NROWS];
__device__ float g_gl[4 * NROWS];
__device__ float g_s[2 * DDIM];
__device__ float g_summ[2 * DDIM];
__device__ float g_rp[NCHUNK][4][NROWS];  // row partials: aaS,aaM,abS,abM
__device__ float g_cp[4][NIB][NROWS];     // col partials: abS,abM,bbS,bbM

// ---------------- PTX helpers ----------------------------------------------
__device__ __forceinline__ uint32_t smem_u32(const void* p) {
    uint32_t a;
    asm("{ .reg .u64 tmp; cvta.to.shared.u64 tmp, %1; cvt.u32.u64 %0, tmp; }"
        : "=r"(a) : "l"(p));
    return a;
}

__device__ __forceinline__ void ldm4(uint32_t* r, uint32_t addr) {
    asm volatile("ldmatrix.sync.aligned.m8n8.x4.shared.b16 {%0,%1,%2,%3}, [%4];"
                 : "=r"(r[0]), "=r"(r[1]), "=r"(r[2]), "=r"(r[3]) : "r"(addr));
}

__device__ __forceinline__ void mma16816(float* c, const uint32_t* a,
                                         uint32_t b0, uint32_t b1) {
    asm volatile("mma.sync.aligned.m16n8k16.row.col.f32.bf16.bf16.f32 "
                 "{%0,%1,%2,%3}, {%4,%5,%6,%7}, {%8,%9}, {%0,%1,%2,%3};"
                 : "+f"(c[0]), "+f"(c[1]), "+f"(c[2]), "+f"(c[3])
                 : "r"(a[0]), "r"(a[1]), "r"(a[2]), "r"(a[3]), "r"(b0), "r"(b1));
}

__device__ __forceinline__ void mma_fp8(float* c, const uint32_t* a,
                                        uint32_t b0, uint32_t b1) {
    asm volatile("mma.sync.aligned.m16n8k32.row.col.f32.e4m3.e4m3.f32 "
                 "{%0,%1,%2,%3}, {%4,%5,%6,%7}, {%8,%9}, {%0,%1,%2,%3};"
                 : "+f"(c[0]), "+f"(c[1]), "+f"(c[2]), "+f"(c[3])
                 : "r"(a[0]), "r"(a[1]), "r"(a[2]), "r"(a[3]), "r"(b0), "r"(b1));
}

__device__ __forceinline__ void cpa16(uint32_t dst, const void* src) {
    asm volatile("cp.async.cg.shared.global [%0], [%1], 16;"
                 :: "r"(dst), "l"(src) : "memory");
}
#define CP_COMMIT() asm volatile("cp.async.commit_group;" ::: "memory")
template <int N>
__device__ __forceinline__ void cp_wait() {
    asm volatile("cp.async.wait_group %0;" :: "n"(N) : "memory");
}

// ---------------- fused fp32 -> bf16 conversion (all 4 arrays) -------------
#define Z4 (NROWS * DDIM / 4)      // 524288
#define W4 (DDIM * DDIM / 4)       // 65536
#define TOT4 (2 * Z4 + 2 * W4)

__global__ __launch_bounds__(256) void conv_all_kernel(
    const float* __restrict__ z1, const float* __restrict__ z2,
    const float* __restrict__ w1, const float* __restrict__ w2)
{
    for (int i = blockIdx.x * 256 + threadIdx.x; i < TOT4; i += gridDim.x * 256) {
        const float* src;
        __nv_bfloat16* dst;
        int o;
        if (i < Z4)            { src = z1; dst = g_z16a; o = i; }
        else if (i < 2 * Z4)   { src = z2; dst = g_z16b; o = i - Z4; }
        else if (i < 2*Z4+W4)  { src = w1; dst = g_w1s;  o = i - 2*Z4; }
        else                   { src = w2; dst = g_w2s;  o = i - 2*Z4 - W4; }
        float4 v = ((const float4*)src)[o];
        __nv_bfloat162* d = (__nv_bfloat162*)(dst + (size_t)o * 4);
        d[0] = __float22bfloat162_rn(make_float2(v.x, v.y));
        d[1] = __float22bfloat162_rn(make_float2(v.z, v.w));
    }
}

// ---------------- HMMA projector GEMM (3-stage ring) ------------------------
__global__ __launch_bounds__(256, 1) void gemm_hmma_kernel(
    const float* __restrict__ bias, const float* __restrict__ prelu_a, int stage)
{
    extern __shared__ __align__(16) char gsm[];
    const uint32_t u0 = smem_u32(gsm);

    const int t = threadIdx.x, w = t >> 5, lane = t & 31;
    const int I0 = blockIdx.x * 128, J0 = blockIdx.y * 128;
    const int z = blockIdx.z;

    const __nv_bfloat16* __restrict__ A =
        (stage == 1) ? (z ? g_z16b : g_z16a) : (z ? g_T16b : g_T16a);
    const __nv_bfloat16* __restrict__ Wm = (stage == 1) ? g_w1s : g_w2s;

    const int lr16 = lane & 15, lh = lane >> 4;
    const uint32_t aoff = (w * 16 + lr16) * 80 + lh * 16;
    uint32_t boff[8];
    #pragma unroll
    for (int p = 0; p < 8; p++)
        boff[p] = (p * 16 + lr16) * 80 + lh * 16;

    int rr[2], cc8[2];
    uint32_t dd[2];
    #pragma unroll
    for (int q = 0; q < 2; q++) {
        int id = t + q * 256;
        rr[q] = id >> 2; cc8[q] = (id & 3) * 8;
        dd[q] = rr[q] * 80 + (id & 3) * 16;
    }

    float acc[8][2][4];
    #pragma unroll
    for (int p = 0; p < 8; p++)
        #pragma unroll
        for (int h = 0; h < 2; h++)
            #pragma unroll
            for (int q = 0; q < 4; q++) acc[p][h][q] = 0.0f;

    #pragma unroll
    for (int s = 0; s < 2; s++) {
        const uint32_t b = u0 + s * G_STAGE;
        const int kb = s * 32;
        #pragma unroll
        for (int q = 0; q < 2; q++) {
            cpa16(b + dd[q], A + (size_t)(I0 + rr[q]) * DDIM + kb + cc8[q]);
            cpa16(b + 10240 + dd[q], Wm + (size_t)(J0 + rr[q]) * DDIM + kb + cc8[q]);
        }
        CP_COMMIT();
    }

    for (int ck = 0; ck < 16; ck++) {
        cp_wait<1>();
        __syncthreads();
        if (ck + 2 < 16) {
            const uint32_t b = u0 + ((ck + 2) % 3) * G_STAGE;
            const int kb = (ck + 2) * 32;
            #pragma unroll
            for (int q = 0; q < 2; q++) {
                cpa16(b + dd[q], A + (size_t)(I0 + rr[q]) * DDIM + kb + cc8[q]);
                cpa16(b + 10240 + dd[q], Wm + (size_t)(J0 + rr[q]) * DDIM + kb + cc8[q]);
            }
        }
        CP_COMMIT();
        const uint32_t uA = u0 + (ck % 3) * G_STAGE;
        const uint32_t uW = uA + 10240;
        #pragma unroll
        for (int ks = 0; ks < 2; ks++) {
            uint32_t fA[4];
            ldm4(fA, uA + aoff + ks * 32);
            #pragma unroll
            for (int p = 0; p < 8; p++) {
                uint32_t fW[4];
                ldm4(fW, uW + boff[p] + ks * 32);
                mma16816(acc[p][0], fA, fW[0], fW[2]);
                mma16816(acc[p][1], fA, fW[1], fW[3]);
            }
        }
    }

    const int er = lane >> 2, ec = 2 * (lane & 3);
    const int row = I0 + w * 16 + er;
    const bool do_prelu = (prelu_a != nullptr);
    const float pa = do_prelu ? prelu_a[0] : 0.0f;

    __nv_bfloat16* Out = (stage == 1) ? (z ? g_T16b : g_T16a)
                                      : (z ? g_H16b : g_H16a);
    #pragma unroll
    for (int p = 0; p < 8; p++) {
        #pragma unroll
        for (int h = 0; h < 2; h++) {
            int col = J0 + p * 16 + h * 8 + ec;
            float b0 = bias[col], b1 = bias[col + 1];
            float v0 = acc[p][h][0] + b0, v1 = acc[p][h][1] + b1;
            float v2 = acc[p][h][2] + b0, v3 = acc[p][h][3] + b1;
            if (do_prelu) {
                v0 = (v0 >= 0.0f) ? v0 : pa * v0;
                v1 = (v1 >= 0.0f) ? v1 : pa * v1;
                v2 = (v2 >= 0.0f) ? v2 : pa * v2;
                v3 = (v3 >= 0.0f) ? v3 : pa * v3;
            }
            *(__nv_bfloat162*)(Out + (size_t)row * DDIM + col) =
                __float22bfloat162_rn(make_float2(v0, v1));
            *(__nv_bfloat162*)(Out + (size_t)(row + 8) * DDIM + col) =
                __float22bfloat162_rn(make_float2(v2, v3));
        }
    }
}

// ---------------- row L2 normalization (bf16 in -> fp8 e4m3 out, x16) ------
__global__ __launch_bounds__(128) void l2norm_kernel()
{
    const __nv_bfloat16* h = blockIdx.y ? g_H16b : g_H16a;
    uint8_t* o8 = blockIdx.y ? g_b8 : g_a8;
    const int row = blockIdx.x;
    const int t = threadIdx.x;
    const __nv_bfloat162* src = (const __nv_bfloat162*)&h[(size_t)row * DDIM + t*4];
    __nv_bfloat162 h0 = src[0], h1 = src[1];
    float2 f0 = __bfloat1622float2(h0), f1 = __bfloat1622float2(h1);
    float ss = f0.x*f0.x + f0.y*f0.y + f1.x*f1.x + f1.y*f1.y;
    #pragma unroll
    for (int off = 16; off; off >>= 1) ss += __shfl_down_sync(0xffffffffu, ss, off);
    __shared__ float sm[4];
    __shared__ float stot;
    if ((t & 31) == 0) sm[t >> 5] = ss;
    __syncthreads();
    if (t == 0) stot = sm[0] + sm[1] + sm[2] + sm[3];
    __syncthreads();
    float scale = QSCL / fmaxf(sqrtf(stot), L2EPS);
    __nv_fp8x2_storage_t lo = __nv_cvt_float2_to_fp8x2(
        make_float2(f0.x * scale, f0.y * scale), __NV_SATFINITE, __NV_E4M3);
    __nv_fp8x2_storage_t hi = __nv_cvt_float2_to_fp8x2(
        make_float2(f1.x * scale, f1.y * scale), __NV_SATFINITE, __NV_E4M3);
    uint32_t packed = (uint32_t)lo | ((uint32_t)hi << 16);
    *(uint32_t*)(o8 + (size_t)row * DDIM + t * 4) = packed;
}

// ---------------- FP8 similarity kernel (3-stage ring, 128-k slabs) --------
// CTA (Ib, c): I-rows Ib*128..+127; 16 J-tiles of 64 in chunk c, 4 slabs each.
// aa = a_I.a_J^T, ab = a_I.b_J^T, bb = b_I.b_J^T (all scaled x256).
__global__ __launch_bounds__(256, 1) void sim_kernel(const int* __restrict__ mask)
{
    extern __shared__ __align__(16) char dsm[];
    const uint32_t u0 = smem_u32(dsm);
    float* sred = (float*)(dsm + 3 * SIM_STAGE);

    const int t = threadIdx.x, w = t >> 5, lane = t & 31;
    const int Ib = blockIdx.x, c = blockIdx.y;
    const int I = Ib * IT;
    const int Jbase = c * CHUNKJ;

    const int lr16 = lane & 15, lh = lane >> 4;
    const uint32_t aoff = (w * 16 + lr16) * 144 + lh * 16;
    uint32_t boff[4];
    #pragma unroll
    for (int p = 0; p < 4; p++)
        boff[p] = (p * 16 + lr16) * 144 + lh * 16;

    // cp.async mapping: rows of 128B = 8 chunks of 16B
    int rI[4], cI[4];
    uint32_t dI[4];
    #pragma unroll
    for (int q = 0; q < 4; q++) {
        int id = t + q * 256;
        rI[q] = id >> 3; cI[q] = (id & 7) * 16;
        dI[q] = rI[q] * 144 + cI[q];
    }

    const int er = lane >> 2;
    const int ec = 2 * (lane & 3);
    const size_t gr0 = (size_t)(I + w * 16 + er);

    float rs_aa0 = 0, rs_aa1 = 0, rm_aa0 = 0, rm_aa1 = 0;
    float rs_ab0 = 0, rs_ab1 = 0, rm_ab0 = 0, rm_ab1 = 0;

    float acc[3][8][4];
    #pragma unroll
    for (int m = 0; m < 3; m++)
        #pragma unroll
        for (int nb = 0; nb < 8; nb++)
            #pragma unroll
            for (int q = 0; q < 4; q++) acc[m][nb][q] = 0.0f;

    #define SIM_ISSUE(sidx)                                                     \
    do {                                                                        \
        const int _s = (sidx);                                                  \
        const uint32_t _b = u0 + (_s % 3) * SIM_STAGE;                          \
        const int _J0 = Jbase + (_s >> 2) * 64;                                 \
        const int _kb = (_s & 3) * 128;                                         \
        _Pragma("unroll")                                                       \
        for (int q = 0; q < 4; q++) {                                           \
            cpa16(_b + S_AI + dI[q], g_a8 + (size_t)(I + rI[q]) * DDIM + _kb + cI[q]); \
            cpa16(_b + S_BI + dI[q], g_b8 + (size_t)(I + rI[q]) * DDIM + _kb + cI[q]); \
        }                                                                       \
        _Pragma("unroll")                                                       \
        for (int q = 0; q < 2; q++) {                                           \
            cpa16(_b + S_AJ + dI[q], g_a8 + (size_t)(_J0 + rI[q]) * DDIM + _kb + cI[q]); \
            cpa16(_b + S_BJ + dI[q], g_b8 + (size_t)(_J0 + rI[q]) * DDIM + _kb + cI[q]); \
        }                                                                       \
    } while (0)

    SIM_ISSUE(0); CP_COMMIT();
    SIM_ISSUE(1); CP_COMMIT();

    for (int s = 0; s < NSTAGE; s++) {
        cp_wait<1>();
        __syncthreads();
        if (s + 2 < NSTAGE) SIM_ISSUE(s + 2);
        CP_COMMIT();

        const uint32_t bc = u0 + (s % 3) * SIM_STAGE;
        const uint32_t uAI = bc + S_AI, uBI = bc + S_BI;
        const uint32_t uAJ = bc + S_AJ, uBJ = bc + S_BJ;
        #pragma unroll
        for (int ks = 0; ks < 4; ks++) {      // each ks = 32 fp8 k-elements
            uint32_t fA[4], fB[4], fAJ[4][4], fBJ[4][4];
            ldm4(fA, uAI + aoff + ks * 32);
            ldm4(fB, uBI + aoff + ks * 32);
            #pragma unroll
            for (int p = 0; p < 4; p++) {
                ldm4(fAJ[p], uAJ + boff[p] + ks * 32);
                ldm4(fBJ[p], uBJ + boff[p] + ks * 32);
            }
            #pragma unroll
            for (int p = 0; p < 4; p++) {
                mma_fp8(acc[0][2*p],   fA, fAJ[p][0], fAJ[p][2]);
                mma_fp8(acc[0][2*p+1], fA, fAJ[p][1], fAJ[p][3]);
                mma_fp8(acc[1][2*p],   fA, fBJ[p][0], fBJ[p][2]);
                mma_fp8(acc[1][2*p+1], fA, fBJ[p][1], fBJ[p][3]);
                mma_fp8(acc[2][2*p],   fB, fBJ[p][0], fBJ[p][2]);
                mma_fp8(acc[2][2*p+1], fB, fBJ[p][1], fBJ[p][3]);
            }
        }

        if ((s & 3) == 3) {
            // ---- epilogue for tile jt = s>>2 ----
            const int J0 = Jbase + (s >> 2) * 64;
            #pragma unroll
            for (int nb = 0; nb < 8; nb++) {
                const int gc = J0 + nb * 8 + ec;
                int2 m0 = *(const int2*)(mask + gr0 * NROWS + gc);
                int2 m1 = *(const int2*)(mask + (gr0 + 8) * NROWS + gc);
                float m00 = (float)m0.x, m01 = (float)m0.y;
                float m10 = (float)m1.x, m11 = (float)m1.y;

                float ea0 = __expf(acc[0][nb][0] * EXP_SCALE);
                float ea1 = __expf(acc[0][nb][1] * EXP_SCALE);
                float ea2 = __expf(acc[0][nb][2] * EXP_SCALE);
                float ea3 = __expf(acc[0][nb][3] * EXP_SCALE);
                float eb0 = __expf(acc[1][nb][0] * EXP_SCALE);
                float eb1 = __expf(acc[1][nb][1] * EXP_SCALE);
                float eb2 = __expf(acc[1][nb][2] * EXP_SCALE);
                float eb3 = __expf(acc[1][nb][3] * EXP_SCALE);
                float ec0 = __expf(acc[2][nb][0] * EXP_SCALE);
                float ec1 = __expf(acc[2][nb][1] * EXP_SCALE);
                float ec2 = __expf(acc[2][nb][2] * EXP_SCALE);
                float ec3 = __expf(acc[2][nb][3] * EXP_SCALE);

                rs_aa0 += ea0 + ea1;  rm_aa0 += ea0 * m00 + ea1 * m01;
                rs_aa1 += ea2 + ea3;  rm_aa1 += ea2 * m10 + ea3 * m11;
                rs_ab0 += eb0 + eb1;  rm_ab0 += eb0 * m00 + eb1 * m01;
                rs_ab1 += eb2 + eb3;  rm_ab1 += eb2 * m10 + eb3 * m11;

                float v[8];
                v[0] = eb0 + eb2;              v[1] = eb1 + eb3;
                v[2] = eb0 * m00 + eb2 * m10;  v[3] = eb1 * m01 + eb3 * m11;
                v[4] = ec0 + ec2;              v[5] = ec1 + ec3;
                v[6] = ec0 * m00 + ec2 * m10;  v[7] = ec1 * m01 + ec3 * m11;
                #pragma unroll
                for (int q = 0; q < 8; q++) {
                    v[q] += __shfl_down_sync(0xffffffffu, v[q], 16);
                    v[q] += __shfl_down_sync(0xffffffffu, v[q], 8);
                    v[q] += __shfl_down_sync(0xffffffffu, v[q], 4);
                }
                if (lane < 4) {
                    int col = nb * 8 + 2 * lane;
                    sred[(w * 4 + 0) * 64 + col]     = v[0];
                    sred[(w * 4 + 0) * 64 + col + 1] = v[1];
                    sred[(w * 4 + 1) * 64 + col]     = v[2];
                    sred[(w * 4 + 1) * 64 + col + 1] = v[3];
                    sred[(w * 4 + 2) * 64 + col]     = v[4];
                    sred[(w * 4 + 2) * 64 + col + 1] = v[5];
                    sred[(w * 4 + 3) * 64 + col]     = v[6];
                    sred[(w * 4 + 3) * 64 + col + 1] = v[7];
                }
            }
            __syncthreads();
            {
                int q = t >> 6, col = t & 63;
                float sacc = 0.0f;
                #pragma unroll
                for (int ww = 0; ww < 8; ww++)
                    sacc += sred[(ww * 4 + q) * 64 + col];
                g_cp[q][Ib][J0 + col] = sacc;
            }
            #pragma unroll
            for (int m = 0; m < 3; m++)
                #pragma unroll
                for (int nb = 0; nb < 8; nb++)
                    #pragma unroll
                    for (int q = 0; q < 4; q++) acc[m][nb][q] = 0.0f;
        }
    }

    #pragma unroll
    for (int d = 1; d < 4; d <<= 1) {
        rs_aa0 += __shfl_down_sync(0xffffffffu, rs_aa0, d, 4);
        rs_aa1 += __shfl_down_sync(0xffffffffu, rs_aa1, d, 4);
        rm_aa0 += __shfl_down_sync(0xffffffffu, rm_aa0, d, 4);
        rm_aa1 += __shfl_down_sync(0xffffffffu, rm_aa1, d, 4);
        rs_ab0 += __shfl_down_sync(0xffffffffu, rs_ab0, d, 4);
        rs_ab1 += __shfl_down_sync(0xffffffffu, rs_ab1, d, 4);
        rm_ab0 += __shfl_down_sync(0xffffffffu, rm_ab0, d, 4);
        rm_ab1 += __shfl_down_sync(0xffffffffu, rm_ab1, d, 4);
    }
    if ((lane & 3) == 0) {
        int r0 = I + w * 16 + (lane >> 2);
        g_rp[c][0][r0]     = rs_aa0;
        g_rp[c][0][r0 + 8] = rs_aa1;
        g_rp[c][1][r0]     = rm_aa0;
        g_rp[c][1][r0 + 8] = rm_aa1;
        g_rp[c][2][r0]     = rs_ab0;
        g_rp[c][2][r0 + 8] = rs_ab1;
        g_rp[c][3][r0]     = rm_ab0;
        g_rp[c][3][r0 + 8] = rm_ab1;
    }
}

// ---------------- combine partials -> per-row losses ------------------------
__global__ __launch_bounds__(256) void rowloss2_kernel()
{
    int i = blockIdx.x * 256 + threadIdx.x;
    float aas = 0, aam = 0, abs_ = 0, abm = 0;
    #pragma unroll
    for (int c = 0; c < NCHUNK; c++) {
        aas  += g_rp[c][0][i];
        aam  += g_rp[c][1][i];
        abs_ += g_rp[c][2][i];
        abm  += g_rp[c][3][i];
    }
    float cabs = 0, cabm = 0, cbbs = 0, cbbm = 0;
    for (int b = 0; b < NIB; b++) {
        cabs += g_cp[0][b][i];
        cabm += g_cp[1][b][i];
        cbbs += g_cp[2][b][i];
        cbbm += g_cp[3][b][i];
    }
    g_rowloss[i]         = -logf(abm / (aas + abs_ - aam));
    g_rowloss[NROWS + i] = -logf(cabm / (cbbs + cabs - cbbm));
}

// ---------------- column means of z1, z2 (readout s) -----------------------
__global__ __launch_bounds__(512) void colmean_kernel(const float* __restrict__ z1,
                                                      const float* __restrict__ z2)
{
    const float* z = blockIdx.x ? z2 : z1;
    const int t = threadIdx.x;
    float a0 = 0, a1 = 0, a2 = 0, a3 = 0;
    for (int r = 0; r < NROWS; r += 4) {
        a0 += z[(size_t)(r+0) * DDIM + t];
        a1 += z[(size_t)(r+1) * DDIM + t];
        a2 += z[(size_t)(r+2) * DDIM + t];
        a3 += z[(size_t)(r+3) * DDIM + t];
    }
    g_s[blockIdx.x * DDIM + t] = (a0 + a1 + a2 + a3) * (1.0f / NROWS);
}

// ---------------- global projector chain: summ_p = W @ proj(s_p) -----------
__device__ __forceinline__ void mv_stage(const float* __restrict__ Wm,
                                         const float* __restrict__ bias,
                                         const float* vin, float* vout,
                                         float pa, bool prelu_on,
                                         int warp, int lane)
{
    for (int rr = 0; rr < 32; rr++) {
        int o = warp * 32 + rr;
        const float* wr = Wm + (size_t)o * DDIM;
        float acc = 0.0f;
        for (int i = lane; i < DDIM; i += 32) acc += wr[i] * vin[i];
        #pragma unroll
        for (int off = 16; off; off >>= 1) acc += __shfl_down_sync(0xffffffffu, acc, off);
        if (lane == 0) {
            float v = acc + (bias ? bias[o] : 0.0f);
            if (prelu_on) v = (v >= 0.0f) ? v : pa * v;
            vout[o] = v;
        }
    }
}

__global__ __launch_bounds__(512) void gproj_kernel(
    const float* __restrict__ gw1, const float* __restrict__ gb1,
    const float* __restrict__ ga,  const float* __restrict__ gw2,
    const float* __restrict__ gb2, const float* __restrict__ W)
{
    __shared__ float v[DDIM], u[DDIM], hh[DDIM];
    const int p = blockIdx.x;
    const int t = threadIdx.x, warp = t >> 5, lane = t & 31;
    v[t] = g_s[p * DDIM + t];
    __syncthreads();
    mv_stage(gw1, gb1, v, u, ga[0], true, warp, lane);
    __syncthreads();
    mv_stage(gw2, gb2, u, hh, 0.0f, false, warp, lane);
    __syncthreads();
    for (int rr = 0; rr < 32; rr++) {
        int o = warp * 32 + rr;
        const float* wr = W + (size_t)o * DDIM;
        float acc = 0.0f;
        for (int i = lane; i < DDIM; i += 32) acc += wr[i] * hh[i];
        #pragma unroll
        for (int off = 16; off; off >>= 1) acc += __shfl_down_sync(0xffffffffu, acc, off);
        if (lane == 0) g_summ[p * DDIM + o] = acc;
    }
}

// ---------------- per-row discriminator terms ------------------------------
__global__ __launch_bounds__(256) void sigrows_kernel(const float* __restrict__ z1,
                                                      const float* __restrict__ z2)
{
    const int warp = threadIdx.x >> 5, lane = threadIdx.x & 31;
    const int row = blockIdx.x * 8 + warp;
    const float* r1 = z1 + (size_t)row * DDIM;
    const float* r2 = z2 + (size_t)row * DDIM;
    float d11 = 0, d12 = 0, d21 = 0, d22 = 0;
    for (int i = lane; i < DDIM; i += 32) {
        float a = r1[i], b = r2[i];
        float s1 = g_summ[i], s2 = g_summ[DDIM + i];
        d11 += a * s1; d12 += a * s2; d21 += b * s1; d22 += b * s2;
    }
    #pragma unroll
    for (int off = 16; off; off >>= 1) {
        d11 += __shfl_down_sync(0xffffffffu, d11, off);
        d12 += __shfl_down_sync(0xffffffffu, d12, off);
        d21 += __shfl_down_sync(0xffffffffu, d21, off);
        d22 += __shfl_down_sync(0xffffffffu, d22, off);
    }
    if (lane == 0) {
        float sg11 = 1.0f / (1.0f + expf(-d11));
        float sg21 = 1.0f / (1.0f + expf(-d21));
        float sg22 = 1.0f / (1.0f + expf(-d22));
        float sg12 = 1.0f / (1.0f + expf(-d12));
        g_gl[0 * NROWS + row] = -logf(sg11 + EPS_);
        g_gl[1 * NROWS + row] = -logf(1.0f - sg21 + EPS_);
        g_gl[2 * NROWS + row] = -logf(sg22 + EPS_);
        g_gl[3 * NROWS + row] = -logf(1.0f - sg12 + EPS_);
    }
}

// ---------------- final deterministic reduction ----------------------------
__global__ __launch_bounds__(1024) void finalize_kernel(float* __restrict__ out)
{
    __shared__ float red[32];
    float acc[6] = {0, 0, 0, 0, 0, 0};
    for (int i = threadIdx.x; i < NROWS; i += 1024) {
        acc[0] += g_rowloss[i];
        acc[1] += g_rowloss[NROWS + i];
        acc[2] += g_gl[i];
        acc[3] += g_gl[NROWS + i];
        acc[4] += g_gl[2 * NROWS + i];
        acc[5] += g_gl[3 * NROWS + i];
    }
    const int lane = threadIdx.x & 31, warp = threadIdx.x >> 5;
    float tot[6];
    for (int q = 0; q < 6; q++) {
        float v = acc[q];
        #pragma unroll
        for (int off = 16; off; off >>= 1) v += __shfl_down_sync(0xffffffffu, v, off);
        if (lane == 0) red[warp] = v;
        __syncthreads();
        if (warp == 0) {
            float w = red[lane];
            #pragma unroll
            for (int off = 16; off; off >>= 1) w += __shfl_down_sync(0xffffffffu, w, off);
            if (lane == 0) tot[q] = w;
        }
        __syncthreads();
    }
    if (threadIdx.x == 0) {
        const float inv = 1.0f / NROWS;
        float local = 0.5f * (tot[0] + tot[1]) * inv;
        float gl1   = 0.5f * (tot[2] + tot[3]) * inv;
        float gl2   = 0.5f * (tot[4] + tot[5]) * inv;
        float glob  = 0.5f * (gl1 + gl2);
        out[0] = 0.5f * local + 0.5f * glob;   // ALPHA = 0.5
    }
}

// ---------------- launch ----------------------------------------------------
extern "C" void kernel_launch(void* const* d_in, const int* in_sizes, int n_in,
                              void* d_out, int out_size)
{
    const float* z1  = (const float*)d_in[0];
    const float* z2  = (const float*)d_in[1];
    const float* lw1 = (const float*)d_in[2];
    const float* lb1 = (const float*)d_in[3];
    const float* la  = (const float*)d_in[4];
    const float* lw2 = (const float*)d_in[5];
    const float* lb2 = (const float*)d_in[6];
    const float* gw1 = (const float*)d_in[7];
    const float* gb1 = (const float*)d_in[8];
    const float* ga  = (const float*)d_in[9];
    const float* gw2 = (const float*)d_in[10];
    const float* gb2 = (const float*)d_in[11];
    const float* W   = (const float*)d_in[12];
    const int*   mask= (const int*)  d_in[13];
    float* out = (float*)d_out;

    cudaFuncSetAttribute(sim_kernel, cudaFuncAttributeMaxDynamicSharedMemorySize,
                         SIM_SMEM_BYTES);
    cudaFuncSetAttribute(gemm_hmma_kernel, cudaFuncAttributeMaxDynamicSharedMemorySize,
                         GEMM_SMEM_BYTES);

    conv_all_kernel<<<2048, 256>>>(z1, z2, lw1, lw2);

    gemm_hmma_kernel<<<dim3(32, 4, 2), 256, GEMM_SMEM_BYTES>>>(lb1, la, 1);
    gemm_hmma_kernel<<<dim3(32, 4, 2), 256, GEMM_SMEM_BYTES>>>(lb2, nullptr, 2);

    l2norm_kernel<<<dim3(NROWS, 2), 128>>>();

    sim_kernel<<<dim3(NIB, NCHUNK), 256, SIM_SMEM_BYTES>>>(mask);
    rowloss2_kernel<<<NROWS / 256, 256>>>();

    colmean_kernel<<<2, DDIM>>>(z1, z2);
    gproj_kernel<<<2, DDIM>>>(gw1, gb1, ga, gw2, gb2, W);
    sigrows_kernel<<<NROWS / 8, 256>>>(z1, z2);

    finalize_kernel<<<1, 1024>>>(out);
}

// round 9
// speedup vs baseline: 7.0079x; 1.3805x over previous
#include <cuda_runtime.h>
#include <cuda_bf16.h>
#include <cuda_fp8.h>
#include <math.h>
#include <cstdint>

#define NROWS 4096
#define DDIM  512
#define INV_TAU 5.0f
#define EXP_SCALE (INV_TAU / 256.0f)   // fp8 values scaled x16 -> dot x256
#define QSCL 16.0f
#define EPS_  1e-15f
#define L2EPS 1e-12f

#define NCHUNK 4
#define CHUNKJ (NROWS / NCHUNK)   // 1024
#define IT 128
#define NIB (NROWS / IT)          // 32

// sim kernel: 3-stage ring of 128-wide fp8 k-slabs, row stride 144B
#define S_AI 0
#define S_BI 18432
#define S_AJ 36864
#define S_BJ 46080
#define SIM_STAGE 55296
#define SIM_SMEM_BYTES (3 * SIM_STAGE + 8192)
#define NSTAGE 64          // 16 J-tiles x 4 slabs

// gemm kernel: 3-stage ring of 32-wide bf16 k-slabs, row stride 80B
#define G_STAGE 20480
#define GEMM_SMEM_BYTES (3 * G_STAGE)

typedef unsigned long long u64;

// ---------------- scratch (static device allocations; no cudaMalloc) ------
__device__ __nv_bfloat16 g_z16a[NROWS * DDIM];
__device__ __nv_bfloat16 g_z16b[NROWS * DDIM];
__device__ __nv_bfloat16 g_T16a[NROWS * DDIM];
__device__ __nv_bfloat16 g_T16b[NROWS * DDIM];
__device__ __nv_bfloat16 g_H16a[NROWS * DDIM];
__device__ __nv_bfloat16 g_H16b[NROWS * DDIM];
__device__ __nv_bfloat16 g_w1s[DDIM * DDIM];
__device__ __nv_bfloat16 g_w2s[DDIM * DDIM];
__device__ uint8_t g_a8[NROWS * DDIM];   // fp8 e4m3, scaled x16
__device__ uint8_t g_b8[NROWS * DDIM];
__device__ float g_rowloss[2 * NROWS];
__device__ float g_gl[4 * NROWS];
__device__ float g_s[2 * DDIM];
__device__ float g_smp[2][16][DDIM];      // colmean partials
__device__ float g_summ[2 * DDIM];
__device__ float g_rp[NCHUNK][4][NROWS];  // row partials: aaS,aaM,abS,abM
__device__ float g_cp[4][NIB][NROWS];     // col partials: abS,abM,bbS,bbM

// ---------------- PTX helpers ----------------------------------------------
__device__ __forceinline__ uint32_t smem_u32(const void* p) {
    uint32_t a;
    asm("{ .reg .u64 tmp; cvta.to.shared.u64 tmp, %1; cvt.u32.u64 %0, tmp; }"
        : "=r"(a) : "l"(p));
    return a;
}

__device__ __forceinline__ void ldm4(uint32_t* r, uint32_t addr) {
    asm volatile("ldmatrix.sync.aligned.m8n8.x4.shared.b16 {%0,%1,%2,%3}, [%4];"
                 : "=r"(r[0]), "=r"(r[1]), "=r"(r[2]), "=r"(r[3]) : "r"(addr));
}

__device__ __forceinline__ void mma16816(float* c, const uint32_t* a,
                                         uint32_t b0, uint32_t b1) {
    asm volatile("mma.sync.aligned.m16n8k16.row.col.f32.bf16.bf16.f32 "
                 "{%0,%1,%2,%3}, {%4,%5,%6,%7}, {%8,%9}, {%0,%1,%2,%3};"
                 : "+f"(c[0]), "+f"(c[1]), "+f"(c[2]), "+f"(c[3])
                 : "r"(a[0]), "r"(a[1]), "r"(a[2]), "r"(a[3]), "r"(b0), "r"(b1));
}

__device__ __forceinline__ void mma_fp8(float* c, const uint32_t* a,
                                        uint32_t b0, uint32_t b1) {
    asm volatile("mma.sync.aligned.m16n8k32.row.col.f32.e4m3.e4m3.f32 "
                 "{%0,%1,%2,%3}, {%4,%5,%6,%7}, {%8,%9}, {%0,%1,%2,%3};"
                 : "+f"(c[0]), "+f"(c[1]), "+f"(c[2]), "+f"(c[3])
                 : "r"(a[0]), "r"(a[1]), "r"(a[2]), "r"(a[3]), "r"(b0), "r"(b1));
}

__device__ __forceinline__ void cpa16(uint32_t dst, const void* src) {
    asm volatile("cp.async.cg.shared.global [%0], [%1], 16;"
                 :: "r"(dst), "l"(src) : "memory");
}
#define CP_COMMIT() asm volatile("cp.async.commit_group;" ::: "memory")
template <int N>
__device__ __forceinline__ void cp_wait() {
    asm volatile("cp.async.wait_group %0;" :: "n"(N) : "memory");
}

// ---------------- fused fp32 -> bf16 conversion (all 4 arrays) -------------
#define Z4 (NROWS * DDIM / 4)      // 524288
#define W4 (DDIM * DDIM / 4)       // 65536
#define TOT4 (2 * Z4 + 2 * W4)

__global__ __launch_bounds__(256) void conv_all_kernel(
    const float* __restrict__ z1, const float* __restrict__ z2,
    const float* __restrict__ w1, const float* __restrict__ w2)
{
    for (int i = blockIdx.x * 256 + threadIdx.x; i < TOT4; i += gridDim.x * 256) {
        const float* src;
        __nv_bfloat16* dst;
        int o;
        if (i < Z4)            { src = z1; dst = g_z16a; o = i; }
        else if (i < 2 * Z4)   { src = z2; dst = g_z16b; o = i - Z4; }
        else if (i < 2*Z4+W4)  { src = w1; dst = g_w1s;  o = i - 2*Z4; }
        else                   { src = w2; dst = g_w2s;  o = i - 2*Z4 - W4; }
        float4 v = ((const float4*)src)[o];
        __nv_bfloat162* d = (__nv_bfloat162*)(dst + (size_t)o * 4);
        d[0] = __float22bfloat162_rn(make_float2(v.x, v.y));
        d[1] = __float22bfloat162_rn(make_float2(v.z, v.w));
    }
}

// ---------------- HMMA projector GEMM (3-stage ring) ------------------------
__global__ __launch_bounds__(256, 1) void gemm_hmma_kernel(
    const float* __restrict__ bias, const float* __restrict__ prelu_a, int stage)
{
    extern __shared__ __align__(16) char gsm[];
    const uint32_t u0 = smem_u32(gsm);

    const int t = threadIdx.x, w = t >> 5, lane = t & 31;
    const int I0 = blockIdx.x * 128, J0 = blockIdx.y * 128;
    const int z = blockIdx.z;

    const __nv_bfloat16* __restrict__ A =
        (stage == 1) ? (z ? g_z16b : g_z16a) : (z ? g_T16b : g_T16a);
    const __nv_bfloat16* __restrict__ Wm = (stage == 1) ? g_w1s : g_w2s;

    const int lr16 = lane & 15, lh = lane >> 4;
    const uint32_t aoff = (w * 16 + lr16) * 80 + lh * 16;
    uint32_t boff[8];
    #pragma unroll
    for (int p = 0; p < 8; p++)
        boff[p] = (p * 16 + lr16) * 80 + lh * 16;

    int rr[2], cc8[2];
    uint32_t dd[2];
    #pragma unroll
    for (int q = 0; q < 2; q++) {
        int id = t + q * 256;
        rr[q] = id >> 2; cc8[q] = (id & 3) * 8;
        dd[q] = rr[q] * 80 + (id & 3) * 16;
    }

    float acc[8][2][4];
    #pragma unroll
    for (int p = 0; p < 8; p++)
        #pragma unroll
        for (int h = 0; h < 2; h++)
            #pragma unroll
            for (int q = 0; q < 4; q++) acc[p][h][q] = 0.0f;

    #pragma unroll
    for (int s = 0; s < 2; s++) {
        const uint32_t b = u0 + s * G_STAGE;
        const int kb = s * 32;
        #pragma unroll
        for (int q = 0; q < 2; q++) {
            cpa16(b + dd[q], A + (size_t)(I0 + rr[q]) * DDIM + kb + cc8[q]);
            cpa16(b + 10240 + dd[q], Wm + (size_t)(J0 + rr[q]) * DDIM + kb + cc8[q]);
        }
        CP_COMMIT();
    }

    for (int ck = 0; ck < 16; ck++) {
        cp_wait<1>();
        __syncthreads();
        if (ck + 2 < 16) {
            const uint32_t b = u0 + ((ck + 2) % 3) * G_STAGE;
            const int kb = (ck + 2) * 32;
            #pragma unroll
            for (int q = 0; q < 2; q++) {
                cpa16(b + dd[q], A + (size_t)(I0 + rr[q]) * DDIM + kb + cc8[q]);
                cpa16(b + 10240 + dd[q], Wm + (size_t)(J0 + rr[q]) * DDIM + kb + cc8[q]);
            }
        }
        CP_COMMIT();
        const uint32_t uA = u0 + (ck % 3) * G_STAGE;
        const uint32_t uW = uA + 10240;
        #pragma unroll
        for (int ks = 0; ks < 2; ks++) {
            uint32_t fA[4];
            ldm4(fA, uA + aoff + ks * 32);
            #pragma unroll
            for (int p = 0; p < 8; p++) {
                uint32_t fW[4];
                ldm4(fW, uW + boff[p] + ks * 32);
                mma16816(acc[p][0], fA, fW[0], fW[2]);
                mma16816(acc[p][1], fA, fW[1], fW[3]);
            }
        }
    }

    const int er = lane >> 2, ec = 2 * (lane & 3);
    const int row = I0 + w * 16 + er;
    const bool do_prelu = (prelu_a != nullptr);
    const float pa = do_prelu ? prelu_a[0] : 0.0f;

    __nv_bfloat16* Out = (stage == 1) ? (z ? g_T16b : g_T16a)
                                      : (z ? g_H16b : g_H16a);
    #pragma unroll
    for (int p = 0; p < 8; p++) {
        #pragma unroll
        for (int h = 0; h < 2; h++) {
            int col = J0 + p * 16 + h * 8 + ec;
            float b0 = bias[col], b1 = bias[col + 1];
            float v0 = acc[p][h][0] + b0, v1 = acc[p][h][1] + b1;
            float v2 = acc[p][h][2] + b0, v3 = acc[p][h][3] + b1;
            if (do_prelu) {
                v0 = (v0 >= 0.0f) ? v0 : pa * v0;
                v1 = (v1 >= 0.0f) ? v1 : pa * v1;
                v2 = (v2 >= 0.0f) ? v2 : pa * v2;
                v3 = (v3 >= 0.0f) ? v3 : pa * v3;
            }
            *(__nv_bfloat162*)(Out + (size_t)row * DDIM + col) =
                __float22bfloat162_rn(make_float2(v0, v1));
            *(__nv_bfloat162*)(Out + (size_t)(row + 8) * DDIM + col) =
                __float22bfloat162_rn(make_float2(v2, v3));
        }
    }
}

// ---------------- row L2 normalization (bf16 in -> fp8 e4m3 out, x16) ------
__global__ __launch_bounds__(128) void l2norm_kernel()
{
    const __nv_bfloat16* h = blockIdx.y ? g_H16b : g_H16a;
    uint8_t* o8 = blockIdx.y ? g_b8 : g_a8;
    const int row = blockIdx.x;
    const int t = threadIdx.x;
    const __nv_bfloat162* src = (const __nv_bfloat162*)&h[(size_t)row * DDIM + t*4];
    __nv_bfloat162 h0 = src[0], h1 = src[1];
    float2 f0 = __bfloat1622float2(h0), f1 = __bfloat1622float2(h1);
    float ss = f0.x*f0.x + f0.y*f0.y + f1.x*f1.x + f1.y*f1.y;
    #pragma unroll
    for (int off = 16; off; off >>= 1) ss += __shfl_down_sync(0xffffffffu, ss, off);
    __shared__ float sm[4];
    __shared__ float stot;
    if ((t & 31) == 0) sm[t >> 5] = ss;
    __syncthreads();
    if (t == 0) stot = sm[0] + sm[1] + sm[2] + sm[3];
    __syncthreads();
    float scale = QSCL / fmaxf(sqrtf(stot), L2EPS);
    __nv_fp8x2_storage_t lo = __nv_cvt_float2_to_fp8x2(
        make_float2(f0.x * scale, f0.y * scale), __NV_SATFINITE, __NV_E4M3);
    __nv_fp8x2_storage_t hi = __nv_cvt_float2_to_fp8x2(
        make_float2(f1.x * scale, f1.y * scale), __NV_SATFINITE, __NV_E4M3);
    uint32_t packed = (uint32_t)lo | ((uint32_t)hi << 16);
    *(uint32_t*)(o8 + (size_t)row * DDIM + t * 4) = packed;
}

// ---------------- FP8 similarity kernel (512 threads, 16 warps) -------------
// CTA (Ib, c): I-rows Ib*128..+127; 16 J-tiles of 64 in chunk c, 4 slabs each.
// Warp w: rows (w&7)*16..+15, column half (w>>3)*32..+31 of each J-tile.
__global__ __launch_bounds__(512, 1) void sim_kernel(const int* __restrict__ mask)
{
    extern __shared__ __align__(16) char dsm[];
    const uint32_t u0 = smem_u32(dsm);
    float* sred = (float*)(dsm + 3 * SIM_STAGE);   // 2048 floats

    const int t = threadIdx.x, w = t >> 5, lane = t & 31;
    const int rw = w & 7, ch = w >> 3;
    const int Ib = blockIdx.x, c = blockIdx.y;
    const int I = Ib * IT;
    const int Jbase = c * CHUNKJ;

    const int lr16 = lane & 15, lh = lane >> 4;
    const uint32_t aoff = (rw * 16 + lr16) * 144 + lh * 16;
    uint32_t boff[2];
    #pragma unroll
    for (int p = 0; p < 2; p++)
        boff[p] = ((ch * 2 + p) * 16 + lr16) * 144 + lh * 16;

    // cp.async mapping: 512 threads; AI/BI 1024 chunks (2/thread), AJ/BJ 512 (1/thread)
    int rI[2], cI[2];
    uint32_t dI[2];
    #pragma unroll
    for (int q = 0; q < 2; q++) {
        int id = t + q * 512;
        rI[q] = id >> 3; cI[q] = (id & 7) * 16;
        dI[q] = rI[q] * 144 + cI[q];
    }

    const int er = lane >> 2;
    const int ec = 2 * (lane & 3);
    const size_t gr0 = (size_t)(I + rw * 16 + er);

    float rs_aa0 = 0, rs_aa1 = 0, rm_aa0 = 0, rm_aa1 = 0;
    float rs_ab0 = 0, rs_ab1 = 0, rm_ab0 = 0, rm_ab1 = 0;

    float acc[3][4][4];
    #pragma unroll
    for (int m = 0; m < 3; m++)
        #pragma unroll
        for (int nb = 0; nb < 4; nb++)
            #pragma unroll
            for (int q = 0; q < 4; q++) acc[m][nb][q] = 0.0f;

    #define SIM_ISSUE(sidx)                                                     \
    do {                                                                        \
        const int _s = (sidx);                                                  \
        const uint32_t _b = u0 + (_s % 3) * SIM_STAGE;                          \
        const int _J0 = Jbase + (_s >> 2) * 64;                                 \
        const int _kb = (_s & 3) * 128;                                         \
        _Pragma("unroll")                                                       \
        for (int q = 0; q < 2; q++) {                                           \
            cpa16(_b + S_AI + dI[q], g_a8 + (size_t)(I + rI[q]) * DDIM + _kb + cI[q]); \
            cpa16(_b + S_BI + dI[q], g_b8 + (size_t)(I + rI[q]) * DDIM + _kb + cI[q]); \
        }                                                                       \
        cpa16(_b + S_AJ + dI[0], g_a8 + (size_t)(_J0 + rI[0]) * DDIM + _kb + cI[0]); \
        cpa16(_b + S_BJ + dI[0], g_b8 + (size_t)(_J0 + rI[0]) * DDIM + _kb + cI[0]); \
    } while (0)

    SIM_ISSUE(0); CP_COMMIT();
    SIM_ISSUE(1); CP_COMMIT();

    for (int s = 0; s < NSTAGE; s++) {
        cp_wait<1>();
        __syncthreads();
        if (s + 2 < NSTAGE) SIM_ISSUE(s + 2);
        CP_COMMIT();

        const uint32_t bc = u0 + (s % 3) * SIM_STAGE;
        const uint32_t uAI = bc + S_AI, uBI = bc + S_BI;
        const uint32_t uAJ = bc + S_AJ, uBJ = bc + S_BJ;
        #pragma unroll
        for (int ks = 0; ks < 4; ks++) {      // each ks = 32 fp8 k-elements
            uint32_t fA[4], fB[4], fAJ[2][4], fBJ[2][4];
            ldm4(fA, uAI + aoff + ks * 32);
            ldm4(fB, uBI + aoff + ks * 32);
            #pragma unroll
            for (int p = 0; p < 2; p++) {
                ldm4(fAJ[p], uAJ + boff[p] + ks * 32);
                ldm4(fBJ[p], uBJ + boff[p] + ks * 32);
            }
            #pragma unroll
            for (int p = 0; p < 2; p++) {
                mma_fp8(acc[0][2*p],   fA, fAJ[p][0], fAJ[p][2]);
                mma_fp8(acc[0][2*p+1], fA, fAJ[p][1], fAJ[p][3]);
                mma_fp8(acc[1][2*p],   fA, fBJ[p][0], fBJ[p][2]);
                mma_fp8(acc[1][2*p+1], fA, fBJ[p][1], fBJ[p][3]);
                mma_fp8(acc[2][2*p],   fB, fBJ[p][0], fBJ[p][2]);
                mma_fp8(acc[2][2*p+1], fB, fBJ[p][1], fBJ[p][3]);
            }
        }

        if ((s & 3) == 3) {
            // ---- epilogue for tile jt = s>>2 ----
            const int J0 = Jbase + (s >> 2) * 64;
            #pragma unroll
            for (int nb = 0; nb < 4; nb++) {
                const int gc = J0 + (ch * 4 + nb) * 8 + ec;
                int2 m0 = *(const int2*)(mask + gr0 * NROWS + gc);
                int2 m1 = *(const int2*)(mask + (gr0 + 8) * NROWS + gc);
                float m00 = (float)m0.x, m01 = (float)m0.y;
                float m10 = (float)m1.x, m11 = (float)m1.y;

                float ea0 = __expf(acc[0][nb][0] * EXP_SCALE);
                float ea1 = __expf(acc[0][nb][1] * EXP_SCALE);
                float ea2 = __expf(acc[0][nb][2] * EXP_SCALE);
                float ea3 = __expf(acc[0][nb][3] * EXP_SCALE);
                float eb0 = __expf(acc[1][nb][0] * EXP_SCALE);
                float eb1 = __expf(acc[1][nb][1] * EXP_SCALE);
                float eb2 = __expf(acc[1][nb][2] * EXP_SCALE);
                float eb3 = __expf(acc[1][nb][3] * EXP_SCALE);
                float ec0 = __expf(acc[2][nb][0] * EXP_SCALE);
                float ec1 = __expf(acc[2][nb][1] * EXP_SCALE);
                float ec2 = __expf(acc[2][nb][2] * EXP_SCALE);
                float ec3 = __expf(acc[2][nb][3] * EXP_SCALE);

                rs_aa0 += ea0 + ea1;  rm_aa0 += ea0 * m00 + ea1 * m01;
                rs_aa1 += ea2 + ea3;  rm_aa1 += ea2 * m10 + ea3 * m11;
                rs_ab0 += eb0 + eb1;  rm_ab0 += eb0 * m00 + eb1 * m01;
                rs_ab1 += eb2 + eb3;  rm_ab1 += eb2 * m10 + eb3 * m11;

                float v[8];
                v[0] = eb0 + eb2;              v[1] = eb1 + eb3;
                v[2] = eb0 * m00 + eb2 * m10;  v[3] = eb1 * m01 + eb3 * m11;
                v[4] = ec0 + ec2;              v[5] = ec1 + ec3;
                v[6] = ec0 * m00 + ec2 * m10;  v[7] = ec1 * m01 + ec3 * m11;
                #pragma unroll
                for (int q = 0; q < 8; q++) {
                    v[q] += __shfl_down_sync(0xffffffffu, v[q], 16);
                    v[q] += __shfl_down_sync(0xffffffffu, v[q], 8);
                    v[q] += __shfl_down_sync(0xffffffffu, v[q], 4);
                }
                if (lane < 4) {
                    int cl = nb * 8 + 2 * lane;
                    sred[w * 128 + 0 * 32 + cl]     = v[0];
                    sred[w * 128 + 0 * 32 + cl + 1] = v[1];
                    sred[w * 128 + 1 * 32 + cl]     = v[2];
                    sred[w * 128 + 1 * 32 + cl + 1] = v[3];
                    sred[w * 128 + 2 * 32 + cl]     = v[4];
                    sred[w * 128 + 2 * 32 + cl + 1] = v[5];
                    sred[w * 128 + 3 * 32 + cl]     = v[6];
                    sred[w * 128 + 3 * 32 + cl + 1] = v[7];
                }
            }
            __syncthreads();
            if (t < 256) {
                int q = t >> 6, colg = t & 63;
                int ch2 = colg >> 5, cl = colg & 31;
                float sacc = 0.0f;
                #pragma unroll
                for (int r2 = 0; r2 < 8; r2++)
                    sacc += sred[(ch2 * 8 + r2) * 128 + q * 32 + cl];
                g_cp[q][Ib][J0 + colg] = sacc;
            }
            #pragma unroll
            for (int m = 0; m < 3; m++)
                #pragma unroll
                for (int nb = 0; nb < 4; nb++)
                    #pragma unroll
                    for (int q = 0; q < 4; q++) acc[m][nb][q] = 0.0f;
        }
    }

    // ---- combine row partials across column-half warps ----
    #pragma unroll
    for (int d = 1; d < 4; d <<= 1) {
        rs_aa0 += __shfl_down_sync(0xffffffffu, rs_aa0, d, 4);
        rs_aa1 += __shfl_down_sync(0xffffffffu, rs_aa1, d, 4);
        rm_aa0 += __shfl_down_sync(0xffffffffu, rm_aa0, d, 4);
        rm_aa1 += __shfl_down_sync(0xffffffffu, rm_aa1, d, 4);
        rs_ab0 += __shfl_down_sync(0xffffffffu, rs_ab0, d, 4);
        rs_ab1 += __shfl_down_sync(0xffffffffu, rs_ab1, d, 4);
        rm_ab0 += __shfl_down_sync(0xffffffffu, rm_ab0, d, 4);
        rm_ab1 += __shfl_down_sync(0xffffffffu, rm_ab1, d, 4);
    }
    __syncthreads();   // last tile's sred reads done before reuse
    const int r0 = rw * 16 + er;   // local row 0..127 (for er = lane>>2 when lane&3==0)
    if (ch == 1 && (lane & 3) == 0) {
        sred[r0 * 4 + 0] = rs_aa0;  sred[r0 * 4 + 1] = rm_aa0;
        sred[r0 * 4 + 2] = rs_ab0;  sred[r0 * 4 + 3] = rm_ab0;
        sred[(r0 + 8) * 4 + 0] = rs_aa1;  sred[(r0 + 8) * 4 + 1] = rm_aa1;
        sred[(r0 + 8) * 4 + 2] = rs_ab1;  sred[(r0 + 8) * 4 + 3] = rm_ab1;
    }
    __syncthreads();
    if (ch == 0 && (lane & 3) == 0) {
        g_rp[c][0][I + r0]     = rs_aa0 + sred[r0 * 4 + 0];
        g_rp[c][1][I + r0]     = rm_aa0 + sred[r0 * 4 + 1];
        g_rp[c][2][I + r0]     = rs_ab0 + sred[r0 * 4 + 2];
        g_rp[c][3][I + r0]     = rm_ab0 + sred[r0 * 4 + 3];
        g_rp[c][0][I + r0 + 8] = rs_aa1 + sred[(r0 + 8) * 4 + 0];
        g_rp[c][1][I + r0 + 8] = rm_aa1 + sred[(r0 + 8) * 4 + 1];
        g_rp[c][2][I + r0 + 8] = rs_ab1 + sred[(r0 + 8) * 4 + 2];
        g_rp[c][3][I + r0 + 8] = rm_ab1 + sred[(r0 + 8) * 4 + 3];
    }
}

// ---------------- combine partials -> per-row losses ------------------------
__global__ __launch_bounds__(256) void rowloss2_kernel()
{
    int i = blockIdx.x * 256 + threadIdx.x;
    float aas = 0, aam = 0, abs_ = 0, abm = 0;
    #pragma unroll
    for (int c = 0; c < NCHUNK; c++) {
        aas  += g_rp[c][0][i];
        aam  += g_rp[c][1][i];
        abs_ += g_rp[c][2][i];
        abm  += g_rp[c][3][i];
    }
    float cabs = 0, cabm = 0, cbbs = 0, cbbm = 0;
    for (int b = 0; b < NIB; b++) {
        cabs += g_cp[0][b][i];
        cabm += g_cp[1][b][i];
        cbbs += g_cp[2][b][i];
        cbbm += g_cp[3][b][i];
    }
    g_rowloss[i]         = -logf(abm / (aas + abs_ - aam));
    g_rowloss[NROWS + i] = -logf(cabm / (cbbs + cabs - cbbm));
}

// ---------------- column-mean partials (readout s) --------------------------
__global__ __launch_bounds__(512) void colmean_kernel(const float* __restrict__ z1,
                                                      const float* __restrict__ z2)
{
    const float* z = blockIdx.y ? z2 : z1;
    const int rb = blockIdx.x;   // 16 row blocks of 256
    const int t = threadIdx.x;
    float a0 = 0, a1 = 0, a2 = 0, a3 = 0;
    const int r0 = rb * 256;
    for (int r = r0; r < r0 + 256; r += 4) {
        a0 += z[(size_t)(r+0) * DDIM + t];
        a1 += z[(size_t)(r+1) * DDIM + t];
        a2 += z[(size_t)(r+2) * DDIM + t];
        a3 += z[(size_t)(r+3) * DDIM + t];
    }
    g_smp[blockIdx.y][rb][t] = (a0 + a1 + a2 + a3) * (1.0f / NROWS);
}

// ---------------- global projector chain: summ_p = W @ proj(s_p) -----------
__device__ __forceinline__ void mv_stage(const float* __restrict__ Wm,
                                         const float* __restrict__ bias,
                                         const float* vin, float* vout,
                                         float pa, bool prelu_on,
                                         int warp, int lane)
{
    for (int rr = 0; rr < 32; rr++) {
        int o = warp * 32 + rr;
        const float* wr = Wm + (size_t)o * DDIM;
        float acc = 0.0f;
        for (int i = lane; i < DDIM; i += 32) acc += wr[i] * vin[i];
        #pragma unroll
        for (int off = 16; off; off >>= 1) acc += __shfl_down_sync(0xffffffffu, acc, off);
        if (lane == 0) {
            float v = acc + (bias ? bias[o] : 0.0f);
            if (prelu_on) v = (v >= 0.0f) ? v : pa * v;
            vout[o] = v;
        }
    }
}

__global__ __launch_bounds__(512) void gproj_kernel(
    const float* __restrict__ gw1, const float* __restrict__ gb1,
    const float* __restrict__ ga,  const float* __restrict__ gw2,
    const float* __restrict__ gb2, const float* __restrict__ W)
{
    __shared__ float v[DDIM], u[DDIM], hh[DDIM];
    const int p = blockIdx.x;
    const int t = threadIdx.x, warp = t >> 5, lane = t & 31;
    float sv = 0.0f;
    #pragma unroll
    for (int rb = 0; rb < 16; rb++) sv += g_smp[p][rb][t];
    v[t] = sv;
    __syncthreads();
    mv_stage(gw1, gb1, v, u, ga[0], true, warp, lane);
    __syncthreads();
    mv_stage(gw2, gb2, u, hh, 0.0f, false, warp, lane);
    __syncthreads();
    for (int rr = 0; rr < 32; rr++) {
        int o = warp * 32 + rr;
        const float* wr = W + (size_t)o * DDIM;
        float acc = 0.0f;
        for (int i = lane; i < DDIM; i += 32) acc += wr[i] * hh[i];
        #pragma unroll
        for (int off = 16; off; off >>= 1) acc += __shfl_down_sync(0xffffffffu, acc, off);
        if (lane == 0) g_summ[p * DDIM + o] = acc;
    }
}

// ---------------- per-row discriminator terms ------------------------------
__global__ __launch_bounds__(256) void sigrows_kernel(const float* __restrict__ z1,
                                                      const float* __restrict__ z2)
{
    const int warp = threadIdx.x >> 5, lane = threadIdx.x & 31;
    const int row = blockIdx.x * 8 + warp;
    const float* r1 = z1 + (size_t)row * DDIM;
    const float* r2 = z2 + (size_t)row * DDIM;
    float d11 = 0, d12 = 0, d21 = 0, d22 = 0;
    for (int i = lane; i < DDIM; i += 32) {
        float a = r1[i], b = r2[i];
        float s1 = g_summ[i], s2 = g_summ[DDIM + i];
        d11 += a * s1; d12 += a * s2; d21 += b * s1; d22 += b * s2;
    }
    #pragma unroll
    for (int off = 16; off; off >>= 1) {
        d11 += __shfl_down_sync(0xffffffffu, d11, off);
        d12 += __shfl_down_sync(0xffffffffu, d12, off);
        d21 += __shfl_down_sync(0xffffffffu, d21, off);
        d22 += __shfl_down_sync(0xffffffffu, d22, off);
    }
    if (lane == 0) {
        float sg11 = 1.0f / (1.0f + expf(-d11));
        float sg21 = 1.0f / (1.0f + expf(-d21));
        float sg22 = 1.0f / (1.0f + expf(-d22));
        float sg12 = 1.0f / (1.0f + expf(-d12));
        g_gl[0 * NROWS + row] = -logf(sg11 + EPS_);
        g_gl[1 * NROWS + row] = -logf(1.0f - sg21 + EPS_);
        g_gl[2 * NROWS + row] = -logf(sg22 + EPS_);
        g_gl[3 * NROWS + row] = -logf(1.0f - sg12 + EPS_);
    }
}

// ---------------- final deterministic reduction ----------------------------
__global__ __launch_bounds__(1024) void finalize_kernel(float* __restrict__ out)
{
    __shared__ float red[32];
    float acc[6] = {0, 0, 0, 0, 0, 0};
    for (int i = threadIdx.x; i < NROWS; i += 1024) {
        acc[0] += g_rowloss[i];
        acc[1] += g_rowloss[NROWS + i];
        acc[2] += g_gl[i];
        acc[3] += g_gl[NROWS + i];
        acc[4] += g_gl[2 * NROWS + i];
        acc[5] += g_gl[3 * NROWS + i];
    }
    const int lane = threadIdx.x & 31, warp = threadIdx.x >> 5;
    float tot[6];
    for (int q = 0; q < 6; q++) {
        float v = acc[q];
        #pragma unroll
        for (int off = 16; off; off >>= 1) v += __shfl_down_sync(0xffffffffu, v, off);
        if (lane == 0) red[warp] = v;
        __syncthreads();
        if (warp == 0) {
            float w = red[lane];
            #pragma unroll
            for (int off = 16; off; off >>= 1) w += __shfl_down_sync(0xffffffffu, w, off);
            if (lane == 0) tot[q] = w;
        }
        __syncthreads();
    }
    if (threadIdx.x == 0) {
        const float inv = 1.0f / NROWS;
        float local = 0.5f * (tot[0] + tot[1]) * inv;
        float gl1   = 0.5f * (tot[2] + tot[3]) * inv;
        float gl2   = 0.5f * (tot[4] + tot[5]) * inv;
        float glob  = 0.5f * (gl1 + gl2);
        out[0] = 0.5f * local + 0.5f * glob;   // ALPHA = 0.5
    }
}

// ---------------- launch ----------------------------------------------------
extern "C" void kernel_launch(void* const* d_in, const int* in_sizes, int n_in,
                              void* d_out, int out_size)
{
    const float* z1  = (const float*)d_in[0];
    const float* z2  = (const float*)d_in[1];
    const float* lw1 = (const float*)d_in[2];
    const float* lb1 = (const float*)d_in[3];
    const float* la  = (const float*)d_in[4];
    const float* lw2 = (const float*)d_in[5];
    const float* lb2 = (const float*)d_in[6];
    const float* gw1 = (const float*)d_in[7];
    const float* gb1 = (const float*)d_in[8];
    const float* ga  = (const float*)d_in[9];
    const float* gw2 = (const float*)d_in[10];
    const float* gb2 = (const float*)d_in[11];
    const float* W   = (const float*)d_in[12];
    const int*   mask= (const int*)  d_in[13];
    float* out = (float*)d_out;

    cudaFuncSetAttribute(sim_kernel, cudaFuncAttributeMaxDynamicSharedMemorySize,
                         SIM_SMEM_BYTES);
    cudaFuncSetAttribute(gemm_hmma_kernel, cudaFuncAttributeMaxDynamicSharedMemorySize,
                         GEMM_SMEM_BYTES);

    conv_all_kernel<<<2048, 256>>>(z1, z2, lw1, lw2);

    gemm_hmma_kernel<<<dim3(32, 4, 2), 256, GEMM_SMEM_BYTES>>>(lb1, la, 1);
    gemm_hmma_kernel<<<dim3(32, 4, 2), 256, GEMM_SMEM_BYTES>>>(lb2, nullptr, 2);

    l2norm_kernel<<<dim3(NROWS, 2), 128>>>();

    sim_kernel<<<dim3(NIB, NCHUNK), 512, SIM_SMEM_BYTES>>>(mask);
    rowloss2_kernel<<<NROWS / 256, 256>>>();

    colmean_kernel<<<dim3(16, 2), 512>>>(z1, z2);
    gproj_kernel<<<2, DDIM>>>(gw1, gb1, ga, gw2, gb2, W);
    sigrows_kernel<<<NROWS / 8, 256>>>(z1, z2);

    finalize_kernel<<<1, 1024>>>(out);
}